// round 2
// baseline (speedup 1.0000x reference)
#include <cuda_runtime.h>
#include <math.h>

#define N_NODES 100000
#define N_EDGES 800000
#define LN_EPS 1e-5f

// ---------------- scratch (device globals; no allocation allowed) ----------------
__device__ float g_h[(size_t)N_NODES * 160];      // current node state h_t
__device__ float g_C320[(size_t)N_NODES * 320];   // A|B precompute, then reused as U=[h|messages]
__device__ float g_msum[(size_t)N_NODES * 160];   // scatter-add accumulator
__device__ float g_tmp[(size_t)N_NODES * 160];    // GEMM outputs (stride 128 or 160)
__device__ float g_cnt[N_NODES];                  // in-degree (float)
__device__ float g_tw[N_NODES];                   // gate per node
__device__ float g_Wmsg[320 * 160];               // repacked message weights
__device__ float g_bias320[320];                  // [bm | 0]

// ---------------- small helpers ----------------
__device__ __forceinline__ float wsum(float v) {
#pragma unroll
    for (int o = 16; o; o >>= 1) v += __shfl_xor_sync(0xffffffffu, v, o);
    return v;
}

__device__ __forceinline__ unsigned long long pack2(float x, float y) {
    unsigned long long r;
    asm("mov.b64 %0,{%1,%2};" : "=l"(r) : "f"(x), "f"(y));
    return r;
}
__device__ __forceinline__ void ffma2(unsigned long long& d, unsigned long long a, unsigned long long b) {
    asm("fma.rn.f32x2 %0,%1,%2,%3;" : "=l"(d) : "l"(a), "l"(b), "l"(d));
}
__device__ __forceinline__ void unpack2(unsigned long long v, float& x, float& y) {
    asm("mov.b64 {%0,%1},%2;" : "=f"(x), "=f"(y) : "l"(v));
}
__device__ __forceinline__ void red4(float* p, float4 v) {
    asm volatile("red.global.add.v4.f32 [%0], {%1,%2,%3,%4};"
                 :: "l"(p), "f"(v.x), "f"(v.y), "f"(v.z), "f"(v.w) : "memory");
}

// ---------------- generic GEMM: C[M,Nc] = X[M,K] @ W[Nc,K]^T + bias ----------------
// BM=128, BN=128, BK=8, 256 threads, thread tile 8x8, packed f32x2 FMA.
__global__ __launch_bounds__(256) void sgemm_tn(
    const float* __restrict__ X, const float* __restrict__ W,
    const float* __restrict__ bias, float* __restrict__ C,
    int M, int Nc, int K)
{
    __shared__ __align__(16) float As[8][128];
    __shared__ __align__(16) float Bs[8][128];
    const int tid = threadIdx.x;
    const int bm0 = blockIdx.y * 128, bn0 = blockIdx.x * 128;
    const int lrow = tid >> 1, lcol = (tid & 1) * 4;
    const int tx = tid & 15, ty = tid >> 4;
    const int crow = ty * 8, ccol = tx * 8;

    unsigned long long acc[8][4];
#pragma unroll
    for (int i = 0; i < 8; i++)
#pragma unroll
        for (int j = 0; j < 4; j++) acc[i][j] = 0ull;

    const int gr = bm0 + lrow;
    const int gn = bn0 + lrow;
    const float* Xp = X + (size_t)gr * K + lcol;
    const float* Wp = W + (size_t)gn * K + lcol;
    const bool va = (gr < M), vb = (gn < Nc);

    for (int k0 = 0; k0 < K; k0 += 8) {
        float4 av = make_float4(0.f, 0.f, 0.f, 0.f);
        float4 bv = make_float4(0.f, 0.f, 0.f, 0.f);
        if (va) av = *(const float4*)(Xp + k0);
        if (vb) bv = *(const float4*)(Wp + k0);
        As[lcol + 0][lrow] = av.x; As[lcol + 1][lrow] = av.y;
        As[lcol + 2][lrow] = av.z; As[lcol + 3][lrow] = av.w;
        Bs[lcol + 0][lrow] = bv.x; Bs[lcol + 1][lrow] = bv.y;
        Bs[lcol + 2][lrow] = bv.z; Bs[lcol + 3][lrow] = bv.w;
        __syncthreads();
#pragma unroll
        for (int kk = 0; kk < 8; kk++) {
            float4 a0 = *(const float4*)&As[kk][crow];
            float4 a1 = *(const float4*)&As[kk][crow + 4];
            ulonglong2 bq0 = *(const ulonglong2*)&Bs[kk][ccol];
            ulonglong2 bq1 = *(const ulonglong2*)&Bs[kk][ccol + 4];
            unsigned long long b2[4] = { bq0.x, bq0.y, bq1.x, bq1.y };
            unsigned long long a2[8] = {
                pack2(a0.x, a0.x), pack2(a0.y, a0.y), pack2(a0.z, a0.z), pack2(a0.w, a0.w),
                pack2(a1.x, a1.x), pack2(a1.y, a1.y), pack2(a1.z, a1.z), pack2(a1.w, a1.w)
            };
#pragma unroll
            for (int i = 0; i < 8; i++)
#pragma unroll
                for (int j = 0; j < 4; j++) ffma2(acc[i][j], a2[i], b2[j]);
        }
        __syncthreads();
    }

#pragma unroll
    for (int i = 0; i < 8; i++) {
        int r = bm0 + crow + i;
        if (r >= M) break;
        float* Cr = C + (size_t)r * Nc;
#pragma unroll
        for (int j = 0; j < 4; j++) {
            int c0 = bn0 + ccol + 2 * j;
            float vx, vy;
            unpack2(acc[i][j], vx, vy);
            if (c0 < Nc)     Cr[c0]     = vx + bias[c0];
            if (c0 + 1 < Nc) Cr[c0 + 1] = vy + bias[c0 + 1];
        }
    }
}

// ---------------- zero kernels ----------------
__global__ void zero_cnt() {
    int i = blockIdx.x * blockDim.x + threadIdx.x;
    if (i < N_NODES) g_cnt[i] = 0.f;
}
__global__ void zero_msum() {
    int i = blockIdx.x * blockDim.x + threadIdx.x;
    int st = gridDim.x * blockDim.x;
    float4* p = (float4*)g_msum;
    const int n4 = N_NODES * 40;
    for (int k = i; k < n4; k += st) p[k] = make_float4(0.f, 0.f, 0.f, 0.f);
}

// ---------------- degree ----------------
__global__ void degree_kernel(const int* __restrict__ ei) {
    int e = blockIdx.x * blockDim.x + threadIdx.x;
    if (e < N_EDGES) atomicAdd(&g_cnt[ei[N_EDGES + e]], 1.0f);
}

// ---------------- pack message weights: Wmsg[320][160], bias320 = [bm|0] ----------------
__global__ void pack_wmsg(const float* __restrict__ wmL, const float* __restrict__ bmL) {
    int t = blockIdx.x * blockDim.x + threadIdx.x;
    if (t < 320 * 160) {
        int j = t / 160, k = t - j * 160;
        float v = (j < 160) ? wmL[j * 320 + k] : wmL[(j - 160) * 320 + 160 + k];
        g_Wmsg[t] = v;
    }
    if (t < 320) g_bias320[t] = (t < 160) ? bmL[t] : 0.f;
}

// ---------------- encoder epilogue: LN(128)+relu for h, time encoder LN(32)+relu ----------------
__global__ void enc_epi(const float* __restrict__ ts,
                        const float* __restrict__ ge, const float* __restrict__ bee,
                        const float* __restrict__ wt, const float* __restrict__ bt,
                        const float* __restrict__ gt, const float* __restrict__ bet)
{
    int n = (blockIdx.x * blockDim.x + threadIdx.x) >> 5;
    int lane = threadIdx.x & 31;
    if (n >= N_NODES) return;

    const float4* T = (const float4*)(g_tmp + (size_t)n * 128);
    float4 v = T[lane];
    float mean = wsum(v.x + v.y + v.z + v.w) * (1.0f / 128.0f);
    float dx = v.x - mean, dy = v.y - mean, dz = v.z - mean, dw = v.w - mean;
    float var = wsum(dx * dx + dy * dy + dz * dz + dw * dw) * (1.0f / 128.0f);
    float rstd = rsqrtf(var + LN_EPS);
    float4 g = ((const float4*)ge)[lane];
    float4 b = ((const float4*)bee)[lane];
    float4 o;
    o.x = fmaxf(0.f, dx * rstd * g.x + b.x);
    o.y = fmaxf(0.f, dy * rstd * g.y + b.y);
    o.z = fmaxf(0.f, dz * rstd * g.z + b.z);
    o.w = fmaxf(0.f, dw * rstd * g.w + b.w);
    ((float4*)(g_h + (size_t)n * 160))[lane] = o;

    // time encoder: 32 dims, one per lane
    float t0 = ts[n];
    float tv = t0 * wt[lane] + bt[lane];
    float tm = wsum(tv) * (1.0f / 32.0f);
    float td = tv - tm;
    float tvar = wsum(td * td) * (1.0f / 32.0f);
    float tr = rsqrtf(tvar + LN_EPS);
    float tout = fmaxf(0.f, td * tr * gt[lane] + bet[lane]);
    g_h[(size_t)n * 160 + 128 + lane] = tout;
}

// ---------------- edge pass: v = A[src]+B[dst] (+bm already in A), LN, relu, *w, scatter ----------------
__global__ void edge_kernel(const int* __restrict__ ei, const float* __restrict__ ew,
                            const float* __restrict__ gmv, const float* __restrict__ bemv)
{
    int w = (blockIdx.x * blockDim.x + threadIdx.x) >> 5;
    int lane = threadIdx.x & 31;
    if (w >= N_EDGES) return;
    int src = ei[w];
    int dst = ei[N_EDGES + w];
    float ewt = ew[w];

    const float4* S = (const float4*)(g_C320 + (size_t)src * 320);
    const float4* D = (const float4*)(g_C320 + (size_t)dst * 320 + 160);
    const bool two = lane < 8;

    float4 s0 = S[lane], d0 = D[lane];
    float4 v0 = make_float4(s0.x + d0.x, s0.y + d0.y, s0.z + d0.z, s0.w + d0.w);
    float4 v1 = make_float4(0.f, 0.f, 0.f, 0.f);
    if (two) {
        float4 s1 = S[lane + 32], d1 = D[lane + 32];
        v1 = make_float4(s1.x + d1.x, s1.y + d1.y, s1.z + d1.z, s1.w + d1.w);
    }
    float s = v0.x + v0.y + v0.z + v0.w;
    if (two) s += v1.x + v1.y + v1.z + v1.w;
    float mean = wsum(s) * (1.0f / 160.0f);

    float q = (v0.x - mean) * (v0.x - mean) + (v0.y - mean) * (v0.y - mean)
            + (v0.z - mean) * (v0.z - mean) + (v0.w - mean) * (v0.w - mean);
    if (two) q += (v1.x - mean) * (v1.x - mean) + (v1.y - mean) * (v1.y - mean)
                + (v1.z - mean) * (v1.z - mean) + (v1.w - mean) * (v1.w - mean);
    float var = wsum(q) * (1.0f / 160.0f);
    float rstd = rsqrtf(var + LN_EPS);

    float* base = g_msum + (size_t)dst * 160;
    {
        float4 g = ((const float4*)gmv)[lane];
        float4 b = ((const float4*)bemv)[lane];
        float4 o;
        o.x = fmaxf(0.f, (v0.x - mean) * rstd * g.x + b.x) * ewt;
        o.y = fmaxf(0.f, (v0.y - mean) * rstd * g.y + b.y) * ewt;
        o.z = fmaxf(0.f, (v0.z - mean) * rstd * g.z + b.z) * ewt;
        o.w = fmaxf(0.f, (v0.w - mean) * rstd * g.w + b.w) * ewt;
        red4(base + 4 * lane, o);
    }
    if (two) {
        float4 g = ((const float4*)gmv)[lane + 32];
        float4 b = ((const float4*)bemv)[lane + 32];
        float4 o;
        o.x = fmaxf(0.f, (v1.x - mean) * rstd * g.x + b.x) * ewt;
        o.y = fmaxf(0.f, (v1.y - mean) * rstd * g.y + b.y) * ewt;
        o.z = fmaxf(0.f, (v1.z - mean) * rstd * g.z + b.z) * ewt;
        o.w = fmaxf(0.f, (v1.w - mean) * rstd * g.w + b.w) * ewt;
        red4(base + 4 * (lane + 32), o);
    }
}

// ---------------- node pass 1: U=[h|messages] into g_C320, gate tw ----------------
__global__ void node1_kernel(const float* __restrict__ wgv, const float* __restrict__ bgv) {
    int n = (blockIdx.x * blockDim.x + threadIdx.x) >> 5;
    int lane = threadIdx.x & 31;
    if (n >= N_NODES) return;

    float c = g_cnt[n];
    float inv = (c > 0.f) ? 1.f / (c + 1e-8f) : 0.f;

    const float4* H = (const float4*)(g_h + (size_t)n * 160);
    const float4* Ms = (const float4*)(g_msum + (size_t)n * 160);
    float4* U = (float4*)(g_C320 + (size_t)n * 320);
    const bool two = lane < 8;

    float dotp = 0.f;
    {
        float4 h = H[lane];
        U[lane] = h;
        float4 m = Ms[lane];
        U[40 + lane] = make_float4(m.x * inv, m.y * inv, m.z * inv, m.w * inv);
        float4 wg = ((const float4*)wgv)[lane];
        dotp = h.x * wg.x + h.y * wg.y + h.z * wg.z + h.w * wg.w;
    }
    if (two) {
        float4 h = H[lane + 32];
        U[lane + 32] = h;
        float4 m = Ms[lane + 32];
        U[72 + lane] = make_float4(m.x * inv, m.y * inv, m.z * inv, m.w * inv);
        float4 wg = ((const float4*)wgv)[lane + 32];
        dotp += h.x * wg.x + h.y * wg.y + h.z * wg.z + h.w * wg.w;
    }
    float tot = wsum(dotp);
    if (lane == 0) g_tw[n] = 1.f / (1.f + expf(-(tot + bgv[0])));
}

// ---------------- node pass 2: LN+relu of update GEMM, gated blend into g_h ----------------
__global__ void node2_kernel(const float* __restrict__ guv, const float* __restrict__ beuv) {
    int n = (blockIdx.x * blockDim.x + threadIdx.x) >> 5;
    int lane = threadIdx.x & 31;
    if (n >= N_NODES) return;

    const float4* T = (const float4*)(g_tmp + (size_t)n * 160);
    const bool two = lane < 8;
    float4 v0 = T[lane];
    float4 v1 = make_float4(0.f, 0.f, 0.f, 0.f);
    if (two) v1 = T[lane + 32];

    float s = v0.x + v0.y + v0.z + v0.w;
    if (two) s += v1.x + v1.y + v1.z + v1.w;
    float mean = wsum(s) * (1.0f / 160.0f);
    float q = (v0.x - mean) * (v0.x - mean) + (v0.y - mean) * (v0.y - mean)
            + (v0.z - mean) * (v0.z - mean) + (v0.w - mean) * (v0.w - mean);
    if (two) q += (v1.x - mean) * (v1.x - mean) + (v1.y - mean) * (v1.y - mean)
                + (v1.z - mean) * (v1.z - mean) + (v1.w - mean) * (v1.w - mean);
    float var = wsum(q) * (1.0f / 160.0f);
    float rstd = rsqrtf(var + LN_EPS);

    float tw = g_tw[n];
    float4* Hr = (float4*)(g_h + (size_t)n * 160);
    {
        float4 g = ((const float4*)guv)[lane];
        float4 b = ((const float4*)beuv)[lane];
        float4 hn;
        hn.x = fmaxf(0.f, (v0.x - mean) * rstd * g.x + b.x);
        hn.y = fmaxf(0.f, (v0.y - mean) * rstd * g.y + b.y);
        hn.z = fmaxf(0.f, (v0.z - mean) * rstd * g.z + b.z);
        hn.w = fmaxf(0.f, (v0.w - mean) * rstd * g.w + b.w);
        float4 ho = Hr[lane];
        Hr[lane] = make_float4(tw * hn.x + (1.f - tw) * ho.x, tw * hn.y + (1.f - tw) * ho.y,
                               tw * hn.z + (1.f - tw) * ho.z, tw * hn.w + (1.f - tw) * ho.w);
    }
    if (two) {
        float4 g = ((const float4*)guv)[lane + 32];
        float4 b = ((const float4*)beuv)[lane + 32];
        float4 hn;
        hn.x = fmaxf(0.f, (v1.x - mean) * rstd * g.x + b.x);
        hn.y = fmaxf(0.f, (v1.y - mean) * rstd * g.y + b.y);
        hn.z = fmaxf(0.f, (v1.z - mean) * rstd * g.z + b.z);
        hn.w = fmaxf(0.f, (v1.w - mean) * rstd * g.w + b.w);
        float4 ho = Hr[lane + 32];
        Hr[lane + 32] = make_float4(tw * hn.x + (1.f - tw) * ho.x, tw * hn.y + (1.f - tw) * ho.y,
                                    tw * hn.z + (1.f - tw) * ho.z, tw * hn.w + (1.f - tw) * ho.w);
    }
}

// ---------------- output epilogue: row normalize ----------------
__global__ void out_epi(float* __restrict__ out) {
    int n = (blockIdx.x * blockDim.x + threadIdx.x) >> 5;
    int lane = threadIdx.x & 31;
    if (n >= N_NODES) return;
    const float4* T = (const float4*)(g_tmp + (size_t)n * 128);
    float4 v = T[lane];
    float ss = v.x * v.x + v.y * v.y + v.z * v.z + v.w * v.w;
    float norm = sqrtf(wsum(ss));
    float sc = 1.f / fmaxf(norm, 1e-12f);
    ((float4*)(out + (size_t)n * 128))[lane] =
        make_float4(v.x * sc, v.y * sc, v.z * sc, v.w * sc);
}

// ---------------- host orchestration ----------------
extern "C" void kernel_launch(void* const* d_in, const int* in_sizes, int n_in,
                              void* d_out, int out_size)
{
    const float* node_features = (const float*)d_in[0];
    const int*   edge_index    = (const int*)d_in[1];
    const float* edge_weights  = (const float*)d_in[2];
    const float* time_steps    = (const float*)d_in[3];
    const float* w_enc   = (const float*)d_in[4];
    const float* b_enc   = (const float*)d_in[5];
    const float* g_enc   = (const float*)d_in[6];
    const float* be_enc  = (const float*)d_in[7];
    const float* w_time  = (const float*)d_in[8];
    const float* b_time  = (const float*)d_in[9];
    const float* g_time  = (const float*)d_in[10];
    const float* be_time = (const float*)d_in[11];
    const float* wm  = (const float*)d_in[12];
    const float* bm  = (const float*)d_in[13];
    const float* gm  = (const float*)d_in[14];
    const float* bem = (const float*)d_in[15];
    const float* wu  = (const float*)d_in[16];
    const float* bu  = (const float*)d_in[17];
    const float* gu  = (const float*)d_in[18];
    const float* beu = (const float*)d_in[19];
    const float* wg  = (const float*)d_in[20];
    const float* bg  = (const float*)d_in[21];
    const float* w_out = (const float*)d_in[22];
    const float* b_out = (const float*)d_in[23];
    float* out = (float*)d_out;

    // symbol addresses for GEMM args (query only, no allocation)
    static float *p_h = nullptr, *p_C = nullptr, *p_tmp = nullptr, *p_Wm = nullptr, *p_b320 = nullptr;
    cudaGetSymbolAddress((void**)&p_h, g_h);
    cudaGetSymbolAddress((void**)&p_C, g_C320);
    cudaGetSymbolAddress((void**)&p_tmp, g_tmp);
    cudaGetSymbolAddress((void**)&p_Wm, g_Wmsg);
    cudaGetSymbolAddress((void**)&p_b320, g_bias320);

    const int GBM = (N_NODES + 127) / 128;          // 782 row-blocks
    const int NODE_WARP_BLOCKS = (N_NODES * 32 + 255) / 256;  // 12500
    const int EDGE_WARP_BLOCKS = (N_EDGES * 32 + 255) / 256;  // 100000

    // degrees (constant across layers)
    zero_cnt<<<(N_NODES + 255) / 256, 256>>>();
    degree_kernel<<<(N_EDGES + 255) / 256, 256>>>(edge_index);

    // encoder: h = relu(LN(x @ w_enc.T + b_enc)); t = relu(LN(ts*w_time + b_time))
    sgemm_tn<<<dim3(1, GBM), 256>>>(node_features, w_enc, b_enc, p_tmp, N_NODES, 128, 128);
    enc_epi<<<NODE_WARP_BLOCKS, 256>>>(time_steps, g_enc, be_enc, w_time, b_time, g_time, be_time);

    for (int l = 0; l < 2; l++) {
        // repack message weights + bias
        pack_wmsg<<<(320 * 160 + 255) / 256, 256>>>(wm + (size_t)l * 160 * 320, bm + l * 160);
        // A|B = h @ Wmsg^T (+ [bm|0])
        sgemm_tn<<<dim3(3, GBM), 256>>>(p_h, p_Wm, p_b320, p_C, N_NODES, 320, 160);
        // scatter-add edge messages
        zero_msum<<<4096, 256>>>();
        edge_kernel<<<EDGE_WARP_BLOCKS, 256>>>(edge_index, edge_weights, gm + l * 160, bem + l * 160);
        // U = [h | messages], gate tw
        node1_kernel<<<NODE_WARP_BLOCKS, 256>>>(wg + l * 160, bg + l);
        // h_new_pre = U @ wu^T + bu
        sgemm_tn<<<dim3(2, GBM), 256>>>(p_C, wu + (size_t)l * 160 * 320, bu + l * 160, p_tmp, N_NODES, 160, 320);
        // h = tw*relu(LN(h_new_pre)) + (1-tw)*h
        node2_kernel<<<NODE_WARP_BLOCKS, 256>>>(gu + l * 160, beu + l * 160);
    }

    // output projection + row normalize
    sgemm_tn<<<dim3(1, GBM), 256>>>(p_h, w_out, b_out, p_tmp, N_NODES, 128, 160);
    out_epi<<<NODE_WARP_BLOCKS, 256>>>(out);
}

// round 4
// speedup vs baseline: 1.0427x; 1.0427x over previous
#include <cuda_runtime.h>
#include <cuda_bf16.h>
#include <math.h>
#include <stdint.h>

#define N_NODES 100000
#define N_EDGES 800000
#define LN_EPS 1e-5f

// ================= scratch (device globals; no allocation allowed) =================
__device__ float g_h[(size_t)N_NODES * 160];      // node state
__device__ float g_C320[(size_t)N_NODES * 320];   // A|B precompute, then U=[h|messages]
__device__ float g_msum[(size_t)N_NODES * 160];   // scatter-add accumulator
__device__ float g_cnt[N_NODES];                  // in-degree
__device__ float g_tw[N_NODES];                   // gate
__device__ float g_bias320[320];                  // [bm | 0]

// bf16 hi/lo split weights (zero-padded K)
__device__ __nv_bfloat16 g_weh[128 * 128], g_wel[128 * 128];   // encoder  [128][128]
__device__ __nv_bfloat16 g_wmh[320 * 192], g_wml[320 * 192];   // message  [320][192]
__device__ __nv_bfloat16 g_wuh[160 * 320], g_wul[160 * 320];   // update   [160][320]
__device__ __nv_bfloat16 g_woh[128 * 192], g_wol[128 * 192];   // output   [128][192]

// ================= helpers =================
__device__ __forceinline__ uint32_t smem_u32(const void* p) {
    uint32_t a;
    asm("{ .reg .u64 t; cvta.to.shared.u64 t, %1; cvt.u32.u64 %0, t; }" : "=r"(a) : "l"(p));
    return a;
}
#define SWZ128(o) ((o) ^ (((o) >> 3) & 0x70))

__device__ __forceinline__ void ldsm4(uint32_t* r, uint32_t addr) {
    asm volatile("ldmatrix.sync.aligned.m8n8.x4.shared.b16 {%0,%1,%2,%3}, [%4];"
        : "=r"(r[0]), "=r"(r[1]), "=r"(r[2]), "=r"(r[3]) : "r"(addr));
}
__device__ __forceinline__ void ldsm2(uint32_t* r, uint32_t addr) {
    asm volatile("ldmatrix.sync.aligned.m8n8.x2.shared.b16 {%0,%1}, [%2];"
        : "=r"(r[0]), "=r"(r[1]) : "r"(addr));
}
__device__ __forceinline__ void mma16816(float* d, const uint32_t* a, const uint32_t* b) {
    asm volatile("mma.sync.aligned.m16n8k16.row.col.f32.bf16.bf16.f32 "
        "{%0,%1,%2,%3},{%4,%5,%6,%7},{%8,%9},{%0,%1,%2,%3};"
        : "+f"(d[0]), "+f"(d[1]), "+f"(d[2]), "+f"(d[3])
        : "r"(a[0]), "r"(a[1]), "r"(a[2]), "r"(a[3]), "r"(b[0]), "r"(b[1]));
}
__device__ __forceinline__ void split2(float a, float b, uint32_t& hi, uint32_t& lo) {
    __nv_bfloat16 ha = __float2bfloat16(a), hb = __float2bfloat16(b);
    __nv_bfloat16 la = __float2bfloat16(a - __bfloat162float(ha));
    __nv_bfloat16 lb = __float2bfloat16(b - __bfloat162float(hb));
    hi = (uint32_t)__bfloat16_as_ushort(ha) | ((uint32_t)__bfloat16_as_ushort(hb) << 16);
    lo = (uint32_t)__bfloat16_as_ushort(la) | ((uint32_t)__bfloat16_as_ushort(lb) << 16);
}
__device__ __forceinline__ float wsum(float v) {
#pragma unroll
    for (int o = 16; o; o >>= 1) v += __shfl_xor_sync(0xffffffffu, v, o);
    return v;
}
__device__ __forceinline__ void red4(float* p, float4 v) {
    asm volatile("red.global.add.v4.f32 [%0], {%1,%2,%3,%4};"
                 :: "l"(p), "f"(v.x), "f"(v.y), "f"(v.z), "f"(v.w) : "memory");
}

// ================= tensor-core GEMM (mma.sync bf16x3 split), fused epilogues ======
// D[128, NT] tile = X[128, Kact] @ W[NT, KPAD]^T (zero-padded).  EPI:
//   0: bias + store fp32 to Y (+n0 col offset), stride ldy            (message precompute)
//   1: bias + LN(NT)+relu -> Y cols 0..127 (ldy); time enc cols 128..159 (encoder)
//   2: bias + LN(NT)+relu + gate blend into w0 (node update)
//   3: bias + row L2-normalize -> Y (output projection)
template<int NT, int KPAD, int EPI>
__global__ __launch_bounds__(256) void gemm_tc(
    const float* __restrict__ X, int ldx, int Kact,
    const __nv_bfloat16* __restrict__ Wh, const __nv_bfloat16* __restrict__ Wl,
    const float* __restrict__ bias,
    float* __restrict__ Y, int ldy,
    const float* __restrict__ a0, const float* __restrict__ a1,
    const float* __restrict__ a2, const float* __restrict__ a3,
    const float* __restrict__ a4, const float* __restrict__ a5,
    const float* __restrict__ a6,
    float* __restrict__ w0)
{
    extern __shared__ __align__(16) char dsm[];
    char* base = (char*)((((uintptr_t)dsm) + 1023) & ~(uintptr_t)1023);
    const uint32_t sb = smem_u32(base);
    constexpr int A_HI = 0, A_LO = 16384, B_HI = 32768;
    constexpr int B_LO = 32768 + NT * 128;
    constexpr int NW = NT / 2;          // cols per warp (N-dim)
    constexpr int NTILES = NW / 8;      // 8-col tiles per warp
    const int tid = threadIdx.x, wid = tid >> 5, lane = tid & 31;
    const int wm = wid & 3, wn = wid >> 2;
    const int bm0 = blockIdx.y * 128, n0 = blockIdx.x * NT;

    float acc[2][NTILES][4];
#pragma unroll
    for (int m = 0; m < 2; m++)
#pragma unroll
        for (int t = 0; t < NTILES; t++)
#pragma unroll
            for (int j = 0; j < 4; j++) acc[m][t][j] = 0.f;

    const int grA = bm0 + tid;
    const bool rvA = (tid < 128) && (grA < N_NODES);
    const float* xrow = X + (size_t)(bm0 + (tid & 127)) * ldx;

    constexpr int NCHUNK = KPAD / 64;
    for (int ch = 0; ch < NCHUNK; ch++) {
        const int c0 = ch * 64;
        if (tid < 128) {
            // A: row tid, cols c0..c0+63, split hi/lo, SW128 store (128B rows)
#pragma unroll
            for (int i = 0; i < 8; i++) {
                int c = c0 + i * 8;
                float v0 = 0, v1 = 0, v2 = 0, v3 = 0, v4 = 0, v5 = 0, v6 = 0, v7 = 0;
                if (rvA && c + 8 <= Kact) {
                    float4 f0 = *(const float4*)(xrow + c);
                    float4 f1 = *(const float4*)(xrow + c + 4);
                    v0 = f0.x; v1 = f0.y; v2 = f0.z; v3 = f0.w;
                    v4 = f1.x; v5 = f1.y; v6 = f1.z; v7 = f1.w;
                }
                uint4 ph, pl;
                split2(v0, v1, ph.x, pl.x); split2(v2, v3, ph.y, pl.y);
                split2(v4, v5, ph.z, pl.z); split2(v6, v7, ph.w, pl.w);
                uint32_t off = SWZ128((uint32_t)(tid * 128 + i * 16));
                *(uint4*)(base + A_HI + off) = ph;
                *(uint4*)(base + A_LO + off) = pl;
            }
        } else {
            // B: copy pre-split weights (128B per row per buffer)
            for (int r = tid - 128; r < NT; r += 128) {
                const uint4* sh = (const uint4*)(Wh + (size_t)(n0 + r) * KPAD + c0);
                const uint4* sl = (const uint4*)(Wl + (size_t)(n0 + r) * KPAD + c0);
#pragma unroll
                for (int i = 0; i < 8; i++) {
                    uint32_t off = SWZ128((uint32_t)(r * 128 + i * 16));
                    *(uint4*)(base + B_HI + off) = sh[i];
                    *(uint4*)(base + B_LO + off) = sl[i];
                }
            }
        }
        __syncthreads();

        // compute: 4 k16 steps over this 64-col chunk
#pragma unroll
        for (int ks = 0; ks < 4; ks++) {
            uint32_t ah[2][4], al[2][4];
            const int arow = wm * 32 + (lane & 15);
            const int akb = ks * 32 + ((lane >> 4) << 4);
            {
                uint32_t o0 = SWZ128((uint32_t)(arow * 128 + akb));
                ldsm4(ah[0], sb + A_HI + o0);
                ldsm4(al[0], sb + A_LO + o0);
                uint32_t o1 = SWZ128((uint32_t)((arow + 16) * 128 + akb));
                ldsm4(ah[1], sb + A_HI + o1);
                ldsm4(al[1], sb + A_LO + o1);
            }
#pragma unroll
            for (int nt = 0; nt < NTILES; nt++) {
                const int brow = wn * NW + nt * 8 + (lane & 7);
                const int bkb = ks * 32 + ((lane >> 3) & 1) * 16;
                uint32_t bo = SWZ128((uint32_t)(brow * 128 + bkb));
                uint32_t bh[2], bl[2];
                ldsm2(bh, sb + B_HI + bo);
                ldsm2(bl, sb + B_LO + bo);
                mma16816(acc[0][nt], ah[0], bh);
                mma16816(acc[0][nt], ah[0], bl);
                mma16816(acc[0][nt], al[0], bh);
                mma16816(acc[1][nt], ah[1], bh);
                mma16816(acc[1][nt], ah[1], bl);
                mma16816(acc[1][nt], al[1], bh);
            }
        }
        __syncthreads();
    }

    // ---------------- stage D in SMEM (reuse buffers), then row-wise epilogue -----
    float* Dsm = (float*)base;   // [128][NT]
#pragma unroll
    for (int mb = 0; mb < 2; mb++) {
        const int r0 = wm * 32 + mb * 16 + (lane >> 2);
        const int c0 = wn * NW + (lane & 3) * 2;
#pragma unroll
        for (int nt = 0; nt < NTILES; nt++) {
            *(float2*)&Dsm[r0 * NT + c0 + nt * 8] = make_float2(acc[mb][nt][0], acc[mb][nt][1]);
            *(float2*)&Dsm[(r0 + 8) * NT + c0 + nt * 8] = make_float2(acc[mb][nt][2], acc[mb][nt][3]);
        }
    }
    __syncthreads();

    constexpr int NJ = NT / 32;   // elements per lane per row
    for (int rr = 0; rr < 16; rr++) {
        const int r = wid * 16 + rr;
        const int gr = bm0 + r;
        const bool rv = gr < N_NODES;
        float v[NJ];
#pragma unroll
        for (int j = 0; j < NJ; j++) {
            int c = lane + 32 * j;
            v[j] = Dsm[r * NT + c] + bias[(EPI == 0 ? n0 : 0) + c];
        }

        if (EPI == 0) {
            if (rv) {
#pragma unroll
                for (int j = 0; j < NJ; j++)
                    Y[(size_t)gr * ldy + n0 + lane + 32 * j] = v[j];
            }
        } else if (EPI == 1 || EPI == 2) {
            float s = 0.f, q = 0.f;
#pragma unroll
            for (int j = 0; j < NJ; j++) { s += v[j]; q += v[j] * v[j]; }
            float mean = wsum(s) * (1.f / NT);
            float var = wsum(q) * (1.f / NT) - mean * mean;
            float rstd = rsqrtf(var + LN_EPS);
            if (rv) {
                if (EPI == 1) {
#pragma unroll
                    for (int j = 0; j < NJ; j++) {
                        int c = lane + 32 * j;
                        Y[(size_t)gr * ldy + c] =
                            fmaxf(0.f, (v[j] - mean) * rstd * a0[c] + a1[c]);
                    }
                    // time encoder (32 dims, one per lane)
                    float t0 = a2[gr];
                    float tv = t0 * a3[lane] + a4[lane];
                    float tm = wsum(tv) * (1.f / 32.f);
                    float td = tv - tm;
                    float tvar = wsum(td * td) * (1.f / 32.f);
                    float tr = rsqrtf(tvar + LN_EPS);
                    Y[(size_t)gr * ldy + 128 + lane] =
                        fmaxf(0.f, td * tr * a5[lane] + a6[lane]);
                } else {
                    float tw = a2[gr];
#pragma unroll
                    for (int j = 0; j < NJ; j++) {
                        int c = lane + 32 * j;
                        float hn = fmaxf(0.f, (v[j] - mean) * rstd * a0[c] + a1[c]);
                        float ho = w0[(size_t)gr * 160 + c];
                        w0[(size_t)gr * 160 + c] = tw * hn + (1.f - tw) * ho;
                    }
                }
            }
        } else {  // EPI == 3
            float q = 0.f;
#pragma unroll
            for (int j = 0; j < NJ; j++) q += v[j] * v[j];
            float sc = 1.f / fmaxf(sqrtf(wsum(q)), 1e-12f);
            if (rv) {
#pragma unroll
                for (int j = 0; j < NJ; j++)
                    Y[(size_t)gr * ldy + lane + 32 * j] = v[j] * sc;
            }
        }
    }
}

// ================= weight split kernels =================
__global__ void split_w(const float* __restrict__ W, __nv_bfloat16* __restrict__ H,
                        __nv_bfloat16* __restrict__ L, int NR, int K, int KPAD) {
    int t = blockIdx.x * blockDim.x + threadIdx.x;
    if (t >= NR * KPAD) return;
    int r = t / KPAD, c = t - r * KPAD;
    float v = (c < K) ? W[r * K + c] : 0.f;
    __nv_bfloat16 h = __float2bfloat16(v);
    H[t] = h;
    L[t] = __float2bfloat16(v - __bfloat162float(h));
}
__global__ void split_msg(const float* __restrict__ wm, const float* __restrict__ bm) {
    int t = blockIdx.x * blockDim.x + threadIdx.x;
    if (t < 320 * 192) {
        int r = t / 192, c = t - r * 192;
        float v = 0.f;
        if (c < 160) v = (r < 160) ? wm[r * 320 + c] : wm[(r - 160) * 320 + 160 + c];
        __nv_bfloat16 h = __float2bfloat16(v);
        g_wmh[t] = h;
        g_wml[t] = __float2bfloat16(v - __bfloat162float(h));
    }
    if (t < 320) g_bias320[t] = (t < 160) ? bm[t] : 0.f;
}

// ================= zero / degree =================
__global__ void zero_cnt() {
    int i = blockIdx.x * blockDim.x + threadIdx.x;
    if (i < N_NODES) g_cnt[i] = 0.f;
}
__global__ void zero_msum() {
    int i = blockIdx.x * blockDim.x + threadIdx.x;
    int st = gridDim.x * blockDim.x;
    float4* p = (float4*)g_msum;
    const int n4 = N_NODES * 40;
    for (int k = i; k < n4; k += st) p[k] = make_float4(0.f, 0.f, 0.f, 0.f);
}
__global__ void degree_kernel(const int* __restrict__ ei) {
    int e = blockIdx.x * blockDim.x + threadIdx.x;
    if (e < N_EDGES) atomicAdd(&g_cnt[ei[N_EDGES + e]], 1.0f);
}

// ================= edge pass =================
__global__ void edge_kernel(const int* __restrict__ ei, const float* __restrict__ ew,
                            const float* __restrict__ gmv, const float* __restrict__ bemv)
{
    int w = (blockIdx.x * blockDim.x + threadIdx.x) >> 5;
    int lane = threadIdx.x & 31;
    if (w >= N_EDGES) return;
    int src = ei[w];
    int dst = ei[N_EDGES + w];
    float ewt = ew[w];

    const float4* S = (const float4*)(g_C320 + (size_t)src * 320);
    const float4* D = (const float4*)(g_C320 + (size_t)dst * 320 + 160);
    const bool two = lane < 8;

    float4 s0 = S[lane], d0 = D[lane];
    float4 v0 = make_float4(s0.x + d0.x, s0.y + d0.y, s0.z + d0.z, s0.w + d0.w);
    float4 v1 = make_float4(0.f, 0.f, 0.f, 0.f);
    if (two) {
        float4 s1 = S[lane + 32], d1 = D[lane + 32];
        v1 = make_float4(s1.x + d1.x, s1.y + d1.y, s1.z + d1.z, s1.w + d1.w);
    }
    float s = v0.x + v0.y + v0.z + v0.w;
    if (two) s += v1.x + v1.y + v1.z + v1.w;
    float mean = wsum(s) * (1.0f / 160.0f);

    float q = (v0.x - mean) * (v0.x - mean) + (v0.y - mean) * (v0.y - mean)
            + (v0.z - mean) * (v0.z - mean) + (v0.w - mean) * (v0.w - mean);
    if (two) q += (v1.x - mean) * (v1.x - mean) + (v1.y - mean) * (v1.y - mean)
                + (v1.z - mean) * (v1.z - mean) + (v1.w - mean) * (v1.w - mean);
    float var = wsum(q) * (1.0f / 160.0f);
    float rstd = rsqrtf(var + LN_EPS);

    float* basep = g_msum + (size_t)dst * 160;
    {
        float4 g = ((const float4*)gmv)[lane];
        float4 b = ((const float4*)bemv)[lane];
        float4 o;
        o.x = fmaxf(0.f, (v0.x - mean) * rstd * g.x + b.x) * ewt;
        o.y = fmaxf(0.f, (v0.y - mean) * rstd * g.y + b.y) * ewt;
        o.z = fmaxf(0.f, (v0.z - mean) * rstd * g.z + b.z) * ewt;
        o.w = fmaxf(0.f, (v0.w - mean) * rstd * g.w + b.w) * ewt;
        red4(basep + 4 * lane, o);
    }
    if (two) {
        float4 g = ((const float4*)gmv)[lane + 32];
        float4 b = ((const float4*)bemv)[lane + 32];
        float4 o;
        o.x = fmaxf(0.f, (v1.x - mean) * rstd * g.x + b.x) * ewt;
        o.y = fmaxf(0.f, (v1.y - mean) * rstd * g.y + b.y) * ewt;
        o.z = fmaxf(0.f, (v1.z - mean) * rstd * g.z + b.z) * ewt;
        o.w = fmaxf(0.f, (v1.w - mean) * rstd * g.w + b.w) * ewt;
        red4(basep + 4 * (lane + 32), o);
    }
}

// ================= node pass 1: U=[h|messages], gate tw =================
__global__ void node1_kernel(const float* __restrict__ wgv, const float* __restrict__ bgv) {
    int n = (blockIdx.x * blockDim.x + threadIdx.x) >> 5;
    int lane = threadIdx.x & 31;
    if (n >= N_NODES) return;

    float c = g_cnt[n];
    float inv = (c > 0.f) ? 1.f / (c + 1e-8f) : 0.f;

    const float4* H = (const float4*)(g_h + (size_t)n * 160);
    const float4* Ms = (const float4*)(g_msum + (size_t)n * 160);
    float4* U = (float4*)(g_C320 + (size_t)n * 320);
    const bool two = lane < 8;

    float dotp = 0.f;
    {
        float4 h = H[lane];
        U[lane] = h;
        float4 m = Ms[lane];
        U[40 + lane] = make_float4(m.x * inv, m.y * inv, m.z * inv, m.w * inv);
        float4 wg = ((const float4*)wgv)[lane];
        dotp = h.x * wg.x + h.y * wg.y + h.z * wg.z + h.w * wg.w;
    }
    if (two) {
        float4 h = H[lane + 32];
        U[lane + 32] = h;
        float4 m = Ms[lane + 32];
        U[72 + lane] = make_float4(m.x * inv, m.y * inv, m.z * inv, m.w * inv);
        float4 wg = ((const float4*)wgv)[lane + 32];
        dotp += h.x * wg.x + h.y * wg.y + h.z * wg.z + h.w * wg.w;
    }
    float tot = wsum(dotp);
    if (lane == 0) g_tw[n] = 1.f / (1.f + expf(-(tot + bgv[0])));
}

// ================= host orchestration =================
extern "C" void kernel_launch(void* const* d_in, const int* in_sizes, int n_in,
                              void* d_out, int out_size)
{
    const float* node_features = (const float*)d_in[0];
    const int*   edge_index    = (const int*)d_in[1];
    const float* edge_weights  = (const float*)d_in[2];
    const float* time_steps    = (const float*)d_in[3];
    const float* w_enc   = (const float*)d_in[4];
    const float* b_enc   = (const float*)d_in[5];
    const float* g_enc   = (const float*)d_in[6];
    const float* be_enc  = (const float*)d_in[7];
    const float* w_time  = (const float*)d_in[8];
    const float* b_time  = (const float*)d_in[9];
    const float* g_time  = (const float*)d_in[10];
    const float* be_time = (const float*)d_in[11];
    const float* wm  = (const float*)d_in[12];
    const float* bm  = (const float*)d_in[13];
    const float* gm  = (const float*)d_in[14];
    const float* bem = (const float*)d_in[15];
    const float* wu  = (const float*)d_in[16];
    const float* bu  = (const float*)d_in[17];
    const float* gu  = (const float*)d_in[18];
    const float* beu = (const float*)d_in[19];
    const float* wg  = (const float*)d_in[20];
    const float* bg  = (const float*)d_in[21];
    const float* w_out = (const float*)d_in[22];
    const float* b_out = (const float*)d_in[23];
    float* out = (float*)d_out;

    float *p_h, *p_C, *p_tw, *p_b320;
    __nv_bfloat16 *p_weh, *p_wel, *p_wmh, *p_wml, *p_wuh, *p_wul, *p_woh, *p_wol;
    cudaGetSymbolAddress((void**)&p_h, g_h);
    cudaGetSymbolAddress((void**)&p_C, g_C320);
    cudaGetSymbolAddress((void**)&p_tw, g_tw);
    cudaGetSymbolAddress((void**)&p_b320, g_bias320);
    cudaGetSymbolAddress((void**)&p_weh, g_weh);
    cudaGetSymbolAddress((void**)&p_wel, g_wel);
    cudaGetSymbolAddress((void**)&p_wmh, g_wmh);
    cudaGetSymbolAddress((void**)&p_wml, g_wml);
    cudaGetSymbolAddress((void**)&p_wuh, g_wuh);
    cudaGetSymbolAddress((void**)&p_wul, g_wul);
    cudaGetSymbolAddress((void**)&p_woh, g_woh);
    cudaGetSymbolAddress((void**)&p_wol, g_wol);

    const int GBM = (N_NODES + 127) / 128;                   // 782
    const int NODE_WARP_BLOCKS = (N_NODES * 32 + 255) / 256; // 12500
    const int EDGE_WARP_BLOCKS = (N_EDGES * 32 + 255) / 256; // 100000

    // dynamic smem: max(buffers, D tile) + align pad
    const int SM160 = 128 * 160 * 4 + 1024;   // 82944 (buffers=73728 < 81920)
    const int SM128 = 128 * 128 * 4 + 1024;   // 66560 (buffers=65536)
    cudaFuncSetAttribute(gemm_tc<128, 128, 1>, cudaFuncAttributeMaxDynamicSharedMemorySize, SM128);
    cudaFuncSetAttribute(gemm_tc<160, 192, 0>, cudaFuncAttributeMaxDynamicSharedMemorySize, SM160);
    cudaFuncSetAttribute(gemm_tc<160, 320, 2>, cudaFuncAttributeMaxDynamicSharedMemorySize, SM160);
    cudaFuncSetAttribute(gemm_tc<128, 192, 3>, cudaFuncAttributeMaxDynamicSharedMemorySize, SM128);

    // degrees (constant across layers)
    zero_cnt<<<(N_NODES + 255) / 256, 256>>>();
    degree_kernel<<<(N_EDGES + 255) / 256, 256>>>(edge_index);

    // encoder GEMM + fused LN/relu + time encoder
    split_w<<<(128 * 128 + 255) / 256, 256>>>(w_enc, p_weh, p_wel, 128, 128, 128);
    gemm_tc<128, 128, 1><<<dim3(1, GBM), 256, SM128>>>(
        node_features, 128, 128, p_weh, p_wel, b_enc, p_h, 160,
        g_enc, be_enc, time_steps, w_time, b_time, g_time, be_time, nullptr);

    for (int l = 0; l < 2; l++) {
        split_msg<<<(320 * 192 + 255) / 256, 256>>>(wm + (size_t)l * 160 * 320, bm + l * 160);
        gemm_tc<160, 192, 0><<<dim3(2, GBM), 256, SM160>>>(
            p_h, 160, 160, p_wmh, p_wml, p_b320, p_C, 320,
            nullptr, nullptr, nullptr, nullptr, nullptr, nullptr, nullptr, nullptr);
        zero_msum<<<4096, 256>>>();
        edge_kernel<<<EDGE_WARP_BLOCKS, 256>>>(edge_index, edge_weights, gm + l * 160, bem + l * 160);
        node1_kernel<<<NODE_WARP_BLOCKS, 256>>>(wg + l * 160, bg + l);
        split_w<<<(160 * 320 + 255) / 256, 256>>>(wu + (size_t)l * 160 * 320, p_wuh, p_wul, 160, 320, 320);
        gemm_tc<160, 320, 2><<<dim3(1, GBM), 256, SM160>>>(
            p_C, 320, 320, p_wuh, p_wul, bu + l * 160, p_h, 160,
            gu + l * 160, beu + l * 160, p_tw, nullptr, nullptr, nullptr, nullptr, p_h);
    }

    // output projection + fused row-normalize
    split_w<<<(128 * 192 + 255) / 256, 256>>>(w_out, p_woh, p_wol, 128, 160, 192);
    gemm_tc<128, 192, 3><<<dim3(1, GBM), 256, SM128>>>(
        p_h, 160, 160, p_woh, p_wol, b_out, out, 128,
        nullptr, nullptr, nullptr, nullptr, nullptr, nullptr, nullptr, nullptr);
}

// round 6
// speedup vs baseline: 1.8060x; 1.7321x over previous
#include <cuda_runtime.h>
#include <cuda_bf16.h>
#include <math.h>
#include <stdint.h>

#define N_NODES 100000
#define NROWS_PAD 100096          // 782 * 128
#define N_EDGES 800000
#define LN_EPS 1e-5f

// ================= scratch (device globals; no allocation allowed) =================
__device__ float g_h[(size_t)N_NODES * 160];      // node state fp32
__device__ float g_C320[(size_t)N_NODES * 320];   // message A|B fp32 (edge kernel input)
__device__ float g_msum[(size_t)N_NODES * 160];   // scatter-add accumulator
__device__ float g_cnt[N_NODES];                  // in-degree
__device__ float g_tw[N_NODES];                   // gate
__device__ float g_bias320[320];                  // [bm | 0]

// bf16 hi/lo pre-split GEMM A operands
__device__ __align__(16) __nv_bfloat16 g_ah[(size_t)NROWS_PAD * 128], g_al[(size_t)NROWS_PAD * 128];   // node_features
__device__ __align__(16) __nv_bfloat16 g_hh[(size_t)NROWS_PAD * 192], g_hl[(size_t)NROWS_PAD * 192];   // h (K=160 pad 192)
__device__ __align__(16) __nv_bfloat16 g_uh[(size_t)NROWS_PAD * 320], g_ul[(size_t)NROWS_PAD * 320];   // U=[h|msg]

// bf16 hi/lo split weights (zero-padded K)
__device__ __align__(16) __nv_bfloat16 g_weh[128 * 128], g_wel[128 * 128];   // encoder
__device__ __align__(16) __nv_bfloat16 g_wmh[320 * 192], g_wml[320 * 192];   // message
__device__ __align__(16) __nv_bfloat16 g_wuh[160 * 320], g_wul[160 * 320];   // update
__device__ __align__(16) __nv_bfloat16 g_woh[128 * 192], g_wol[128 * 192];   // output

// ================= helpers =================
__device__ __forceinline__ uint32_t smem_u32(const void* p) {
    uint32_t a;
    asm("{ .reg .u64 t; cvta.to.shared.u64 t, %1; cvt.u32.u64 %0, t; }" : "=r"(a) : "l"(p));
    return a;
}
#define SWZ128(o) ((o) ^ (((o) >> 3) & 0x70))

__device__ __forceinline__ void cpa16(uint32_t dst, const void* src) {
    asm volatile("cp.async.cg.shared.global [%0], [%1], 16;" :: "r"(dst), "l"(src));
}
#define CP_COMMIT() asm volatile("cp.async.commit_group;" ::: "memory")
#define CP_WAIT0()  asm volatile("cp.async.wait_group 0;" ::: "memory")

__device__ __forceinline__ void ldsm4(uint32_t* r, uint32_t addr) {
    asm volatile("ldmatrix.sync.aligned.m8n8.x4.shared.b16 {%0,%1,%2,%3}, [%4];"
        : "=r"(r[0]), "=r"(r[1]), "=r"(r[2]), "=r"(r[3]) : "r"(addr));
}
__device__ __forceinline__ void mma16816(float* d, const uint32_t* a, const uint32_t* b) {
    asm volatile("mma.sync.aligned.m16n8k16.row.col.f32.bf16.bf16.f32 "
        "{%0,%1,%2,%3},{%4,%5,%6,%7},{%8,%9},{%0,%1,%2,%3};"
        : "+f"(d[0]), "+f"(d[1]), "+f"(d[2]), "+f"(d[3])
        : "r"(a[0]), "r"(a[1]), "r"(a[2]), "r"(a[3]), "r"(b[0]), "r"(b[1]));
}
__device__ __forceinline__ void split2(float a, float b, uint32_t& hi, uint32_t& lo) {
    __nv_bfloat16 ha = __float2bfloat16(a), hb = __float2bfloat16(b);
    __nv_bfloat16 la = __float2bfloat16(a - __bfloat162float(ha));
    __nv_bfloat16 lb = __float2bfloat16(b - __bfloat162float(hb));
    hi = (uint32_t)__bfloat16_as_ushort(ha) | ((uint32_t)__bfloat16_as_ushort(hb) << 16);
    lo = (uint32_t)__bfloat16_as_ushort(la) | ((uint32_t)__bfloat16_as_ushort(lb) << 16);
}
__device__ __forceinline__ void st_split1(__nv_bfloat16* H, __nv_bfloat16* L, size_t idx, float v) {
    __nv_bfloat16 h = __float2bfloat16(v);
    H[idx] = h;
    L[idx] = __float2bfloat16(v - __bfloat162float(h));
}
__device__ __forceinline__ void st_split4(__nv_bfloat16* H, __nv_bfloat16* L, size_t idx, float4 v) {
    uint2 hp, lp;
    split2(v.x, v.y, hp.x, lp.x);
    split2(v.z, v.w, hp.y, lp.y);
    *(uint2*)(H + idx) = hp;
    *(uint2*)(L + idx) = lp;
}
__device__ __forceinline__ float wsum(float v) {
#pragma unroll
    for (int o = 16; o; o >>= 1) v += __shfl_xor_sync(0xffffffffu, v, o);
    return v;
}
__device__ __forceinline__ void red4(float* p, float4 v) {
    asm volatile("red.global.add.v4.f32 [%0], {%1,%2,%3,%4};"
                 :: "l"(p), "f"(v.x), "f"(v.y), "f"(v.z), "f"(v.w) : "memory");
}

// ================= tensor-core GEMM (mma.sync bf16x3 split), fused epilogues ======
// D[128, NT] tile = X[128, KPAD] @ W[NT, KPAD]^T (pre-split bf16 hi/lo operands).  EPI:
//   0: bias + store fp32 to Y (+n0 col offset), stride ldy            (message precompute)
//   1: bias + LN(NT)+relu -> Y cols 0..127 (ldy) + g_hh/g_hl split; time enc col 128+lane
//   2: bias + LN(NT)+relu + gate blend into w0 + g_hh/g_hl split (node update)
//   3: bias + row L2-normalize -> Y (output projection)
template<int NT, int KPAD, int EPI>
__global__ __launch_bounds__(256, 2) void gemm_tc(
    const __nv_bfloat16* __restrict__ Xh, const __nv_bfloat16* __restrict__ Xl,
    const __nv_bfloat16* __restrict__ Wh, const __nv_bfloat16* __restrict__ Wl,
    const float* __restrict__ bias,
    float* __restrict__ Y, int ldy,
    const float* __restrict__ a0, const float* __restrict__ a1,
    const float* __restrict__ a2, const float* __restrict__ a3,
    const float* __restrict__ a4, const float* __restrict__ a5,
    const float* __restrict__ a6,
    float* __restrict__ w0)
{
    extern __shared__ __align__(16) char dsm[];
    char* base = (char*)((((uintptr_t)dsm) + 1023) & ~(uintptr_t)1023);
    const uint32_t sb = smem_u32(base);
    constexpr int A_HI = 0, A_LO = 16384, B_HI = 32768;
    constexpr int B_LO = 32768 + NT * 128;
    constexpr int NW = NT / 2;          // cols per warp (N-dim)
    constexpr int NTILES = NW / 8;      // 8-col tiles per warp (even: 8 or 10)
    const int tid = threadIdx.x, wid = tid >> 5, lane = tid & 31;
    const int wm = wid & 3, wn = wid >> 2;
    const int bm0 = blockIdx.y * 128, n0 = blockIdx.x * NT;

    float acc[2][NTILES][4];
#pragma unroll
    for (int m = 0; m < 2; m++)
#pragma unroll
        for (int t = 0; t < NTILES; t++)
#pragma unroll
            for (int j = 0; j < 4; j++) acc[m][t][j] = 0.f;

    constexpr int NCHUNK = KPAD / 64;
    for (int ch = 0; ch < NCHUNK; ch++) {
        const int c0 = ch * 64;
        // ---- A tile: 128 rows x 64 cols bf16 (hi+lo), cp.async 16B segments ----
#pragma unroll
        for (int s = tid; s < 128 * 8; s += 256) {
            int r = s >> 3, i = s & 7;
            uint32_t off = SWZ128((uint32_t)(r * 128 + i * 16));
            const __nv_bfloat16* srcH = Xh + (size_t)(bm0 + r) * KPAD + c0 + i * 8;
            const __nv_bfloat16* srcL = Xl + (size_t)(bm0 + r) * KPAD + c0 + i * 8;
            cpa16(sb + A_HI + off, srcH);
            cpa16(sb + A_LO + off, srcL);
        }
        // ---- B tile: NT rows x 64 cols (hi+lo) ----
        for (int s = tid; s < NT * 8; s += 256) {
            int r = s >> 3, i = s & 7;
            uint32_t off = SWZ128((uint32_t)(r * 128 + i * 16));
            const __nv_bfloat16* srcH = Wh + (size_t)(n0 + r) * KPAD + c0 + i * 8;
            const __nv_bfloat16* srcL = Wl + (size_t)(n0 + r) * KPAD + c0 + i * 8;
            cpa16(sb + B_HI + off, srcH);
            cpa16(sb + B_LO + off, srcL);
        }
        CP_COMMIT();
        CP_WAIT0();
        __syncthreads();

        // ---- compute: 4 k16 steps over this 64-col chunk ----
#pragma unroll
        for (int ks = 0; ks < 4; ks++) {
            uint32_t ah[2][4], al[2][4];
            const int arow = wm * 32 + (lane & 15);
            const int akb = ks * 32 + ((lane >> 4) << 4);
            {
                uint32_t o0 = SWZ128((uint32_t)(arow * 128 + akb));
                ldsm4(ah[0], sb + A_HI + o0);
                ldsm4(al[0], sb + A_LO + o0);
                uint32_t o1 = SWZ128((uint32_t)((arow + 16) * 128 + akb));
                ldsm4(ah[1], sb + A_HI + o1);
                ldsm4(al[1], sb + A_LO + o1);
            }
            const int q = lane >> 3;
            const int browb = wn * NW + ((q >> 1) << 3) + (lane & 7);
            const int bkb = ks * 32 + (q & 1) * 16;
#pragma unroll
            for (int nt = 0; nt < NTILES; nt += 2) {
                uint32_t bo = SWZ128((uint32_t)((browb + nt * 8) * 128 + bkb));
                uint32_t bh4[4], bl4[4];
                ldsm4(bh4, sb + B_HI + bo);
                ldsm4(bl4, sb + B_LO + bo);
                mma16816(acc[0][nt], ah[0], bh4);
                mma16816(acc[0][nt], ah[0], bl4);
                mma16816(acc[0][nt], al[0], bh4);
                mma16816(acc[1][nt], ah[1], bh4);
                mma16816(acc[1][nt], ah[1], bl4);
                mma16816(acc[1][nt], al[1], bh4);
                mma16816(acc[0][nt + 1], ah[0], bh4 + 2);
                mma16816(acc[0][nt + 1], ah[0], bl4 + 2);
                mma16816(acc[0][nt + 1], al[0], bh4 + 2);
                mma16816(acc[1][nt + 1], ah[1], bh4 + 2);
                mma16816(acc[1][nt + 1], ah[1], bl4 + 2);
                mma16816(acc[1][nt + 1], al[1], bh4 + 2);
            }
        }
        __syncthreads();
    }

    // ---------------- stage D in SMEM (reuse buffers), then row-wise epilogue -----
    float* Dsm = (float*)base;   // [128][NT]
#pragma unroll
    for (int mb = 0; mb < 2; mb++) {
        const int r0 = wm * 32 + mb * 16 + (lane >> 2);
        const int c0 = wn * NW + (lane & 3) * 2;
#pragma unroll
        for (int nt = 0; nt < NTILES; nt++) {
            *(float2*)&Dsm[r0 * NT + c0 + nt * 8] = make_float2(acc[mb][nt][0], acc[mb][nt][1]);
            *(float2*)&Dsm[(r0 + 8) * NT + c0 + nt * 8] = make_float2(acc[mb][nt][2], acc[mb][nt][3]);
        }
    }
    __syncthreads();

    constexpr int NJ = NT / 32;   // elements per lane per row
    for (int rr = 0; rr < 16; rr++) {
        const int r = wid * 16 + rr;
        const int gr = bm0 + r;
        const bool rv = gr < N_NODES;
        float v[NJ];
#pragma unroll
        for (int j = 0; j < NJ; j++) {
            int c = lane + 32 * j;
            v[j] = Dsm[r * NT + c] + bias[(EPI == 0 ? n0 : 0) + c];
        }

        if (EPI == 0) {
            if (rv) {
#pragma unroll
                for (int j = 0; j < NJ; j++)
                    Y[(size_t)gr * ldy + n0 + lane + 32 * j] = v[j];
            }
        } else if (EPI == 1 || EPI == 2) {
            float s = 0.f, q = 0.f;
#pragma unroll
            for (int j = 0; j < NJ; j++) { s += v[j]; q += v[j] * v[j]; }
            float mean = wsum(s) * (1.f / NT);
            float var = wsum(q) * (1.f / NT) - mean * mean;
            float rstd = rsqrtf(var + LN_EPS);
            if (rv) {
                if (EPI == 1) {
#pragma unroll
                    for (int j = 0; j < NJ; j++) {
                        int c = lane + 32 * j;
                        float hv = fmaxf(0.f, (v[j] - mean) * rstd * a0[c] + a1[c]);
                        Y[(size_t)gr * ldy + c] = hv;
                        st_split1(g_hh, g_hl, (size_t)gr * 192 + c, hv);
                    }
                    // time encoder (32 dims, one per lane)
                    float t0 = a2[gr];
                    float tv = t0 * a3[lane] + a4[lane];
                    float tm = wsum(tv) * (1.f / 32.f);
                    float td = tv - tm;
                    float tvar = wsum(td * td) * (1.f / 32.f);
                    float tr = rsqrtf(tvar + LN_EPS);
                    float to = fmaxf(0.f, td * tr * a5[lane] + a6[lane]);
                    Y[(size_t)gr * ldy + 128 + lane] = to;
                    st_split1(g_hh, g_hl, (size_t)gr * 192 + 128 + lane, to);
                    g_hh[(size_t)gr * 192 + 160 + lane] = __float2bfloat16(0.f);
                    g_hl[(size_t)gr * 192 + 160 + lane] = __float2bfloat16(0.f);
                } else {
                    float tw = a2[gr];
#pragma unroll
                    for (int j = 0; j < NJ; j++) {
                        int c = lane + 32 * j;
                        float hn = fmaxf(0.f, (v[j] - mean) * rstd * a0[c] + a1[c]);
                        float ho = w0[(size_t)gr * 160 + c];
                        float hv = tw * hn + (1.f - tw) * ho;
                        w0[(size_t)gr * 160 + c] = hv;
                        st_split1(g_hh, g_hl, (size_t)gr * 192 + c, hv);
                    }
                    g_hh[(size_t)gr * 192 + 160 + lane] = __float2bfloat16(0.f);
                    g_hl[(size_t)gr * 192 + 160 + lane] = __float2bfloat16(0.f);
                }
            }
        } else {  // EPI == 3
            float q = 0.f;
#pragma unroll
            for (int j = 0; j < NJ; j++) q += v[j] * v[j];
            float sc = 1.f / fmaxf(sqrtf(wsum(q)), 1e-12f);
            if (rv) {
#pragma unroll
                for (int j = 0; j < NJ; j++)
                    Y[(size_t)gr * ldy + lane + 32 * j] = v[j] * sc;
            }
        }
    }
}

// ================= weight / input split kernels =================
__global__ void split_w(const float* __restrict__ W, __nv_bfloat16* __restrict__ H,
                        __nv_bfloat16* __restrict__ L, int NR, int K, int KPAD) {
    int t = blockIdx.x * blockDim.x + threadIdx.x;
    if (t >= NR * KPAD) return;
    int r = t / KPAD, c = t - r * KPAD;
    float v = (c < K) ? W[r * K + c] : 0.f;
    __nv_bfloat16 h = __float2bfloat16(v);
    H[t] = h;
    L[t] = __float2bfloat16(v - __bfloat162float(h));
}
__global__ void split_msg(const float* __restrict__ wm, const float* __restrict__ bm) {
    int t = blockIdx.x * blockDim.x + threadIdx.x;
    if (t < 320 * 192) {
        int r = t / 192, c = t - r * 192;
        float v = 0.f;
        if (c < 160) v = (r < 160) ? wm[r * 320 + c] : wm[(r - 160) * 320 + 160 + c];
        __nv_bfloat16 h = __float2bfloat16(v);
        g_wmh[t] = h;
        g_wml[t] = __float2bfloat16(v - __bfloat162float(h));
    }
    if (t < 320) g_bias320[t] = (t < 160) ? bm[t] : 0.f;
}

// ================= zero / degree =================
__global__ void zero_cnt() {
    int i = blockIdx.x * blockDim.x + threadIdx.x;
    if (i < N_NODES) g_cnt[i] = 0.f;
}
__global__ void zero_msum() {
    int i = blockIdx.x * blockDim.x + threadIdx.x;
    int st = gridDim.x * blockDim.x;
    float4* p = (float4*)g_msum;
    const int n4 = N_NODES * 40;
    for (int k = i; k < n4; k += st) p[k] = make_float4(0.f, 0.f, 0.f, 0.f);
}
__global__ void degree_kernel(const int* __restrict__ ei) {
    int e = blockIdx.x * blockDim.x + threadIdx.x;
    if (e < N_EDGES) atomicAdd(&g_cnt[ei[N_EDGES + e]], 1.0f);
}

// ================= edge pass =================
__global__ void edge_kernel(const int* __restrict__ ei, const float* __restrict__ ew,
                            const float* __restrict__ gmv, const float* __restrict__ bemv)
{
    int w = (blockIdx.x * blockDim.x + threadIdx.x) >> 5;
    int lane = threadIdx.x & 31;
    if (w >= N_EDGES) return;
    int src = ei[w];
    int dst = ei[N_EDGES + w];
    float ewt = ew[w];

    const float4* S = (const float4*)(g_C320 + (size_t)src * 320);
    const float4* D = (const float4*)(g_C320 + (size_t)dst * 320 + 160);
    const bool two = lane < 8;

    float4 s0 = S[lane], d0 = D[lane];
    float4 v0 = make_float4(s0.x + d0.x, s0.y + d0.y, s0.z + d0.z, s0.w + d0.w);
    float4 v1 = make_float4(0.f, 0.f, 0.f, 0.f);
    if (two) {
        float4 s1 = S[lane + 32], d1 = D[lane + 32];
        v1 = make_float4(s1.x + d1.x, s1.y + d1.y, s1.z + d1.z, s1.w + d1.w);
    }
    float s = v0.x + v0.y + v0.z + v0.w;
    if (two) s += v1.x + v1.y + v1.z + v1.w;
    float mean = wsum(s) * (1.0f / 160.0f);

    float q = (v0.x - mean) * (v0.x - mean) + (v0.y - mean) * (v0.y - mean)
            + (v0.z - mean) * (v0.z - mean) + (v0.w - mean) * (v0.w - mean);
    if (two) q += (v1.x - mean) * (v1.x - mean) + (v1.y - mean) * (v1.y - mean)
                + (v1.z - mean) * (v1.z - mean) + (v1.w - mean) * (v1.w - mean);
    float var = wsum(q) * (1.0f / 160.0f);
    float rstd = rsqrtf(var + LN_EPS);

    float* basep = g_msum + (size_t)dst * 160;
    {
        float4 g = ((const float4*)gmv)[lane];
        float4 b = ((const float4*)bemv)[lane];
        float4 o;
        o.x = fmaxf(0.f, (v0.x - mean) * rstd * g.x + b.x) * ewt;
        o.y = fmaxf(0.f, (v0.y - mean) * rstd * g.y + b.y) * ewt;
        o.z = fmaxf(0.f, (v0.z - mean) * rstd * g.z + b.z) * ewt;
        o.w = fmaxf(0.f, (v0.w - mean) * rstd * g.w + b.w) * ewt;
        red4(basep + 4 * lane, o);
    }
    if (two) {
        float4 g = ((const float4*)gmv)[lane + 32];
        float4 b = ((const float4*)bemv)[lane + 32];
        float4 o;
        o.x = fmaxf(0.f, (v1.x - mean) * rstd * g.x + b.x) * ewt;
        o.y = fmaxf(0.f, (v1.y - mean) * rstd * g.y + b.y) * ewt;
        o.z = fmaxf(0.f, (v1.z - mean) * rstd * g.z + b.z) * ewt;
        o.w = fmaxf(0.f, (v1.w - mean) * rstd * g.w + b.w) * ewt;
        red4(basep + 4 * (lane + 32), o);
    }
}

// ================= node pass 1: U=[h|messages] split to bf16, gate tw =============
__global__ void node1_kernel(const float* __restrict__ wgv, const float* __restrict__ bgv) {
    int n = (blockIdx.x * blockDim.x + threadIdx.x) >> 5;
    int lane = threadIdx.x & 31;
    if (n >= N_NODES) return;

    float c = g_cnt[n];
    float inv = (c > 0.f) ? 1.f / (c + 1e-8f) : 0.f;

    const float4* H = (const float4*)(g_h + (size_t)n * 160);
    const float4* Ms = (const float4*)(g_msum + (size_t)n * 160);
    const bool two = lane < 8;
    const size_t ub = (size_t)n * 320;

    float dotp = 0.f;
    {
        float4 h = H[lane];
        st_split4(g_uh, g_ul, ub + 4 * lane, h);
        float4 m = Ms[lane];
        float4 mm = make_float4(m.x * inv, m.y * inv, m.z * inv, m.w * inv);
        st_split4(g_uh, g_ul, ub + 160 + 4 * lane, mm);
        float4 wg = ((const float4*)wgv)[lane];
        dotp = h.x * wg.x + h.y * wg.y + h.z * wg.z + h.w * wg.w;
    }
    if (two) {
        float4 h = H[lane + 32];
        st_split4(g_uh, g_ul, ub + 128 + 4 * lane, h);
        float4 m = Ms[lane + 32];
        float4 mm = make_float4(m.x * inv, m.y * inv, m.z * inv, m.w * inv);
        st_split4(g_uh, g_ul, ub + 160 + 128 + 4 * lane, mm);
        float4 wg = ((const float4*)wgv)[lane + 32];
        dotp += h.x * wg.x + h.y * wg.y + h.z * wg.z + h.w * wg.w;
    }
    float tot = wsum(dotp);
    if (lane == 0) g_tw[n] = 1.f / (1.f + expf(-(tot + bgv[0])));
}

// ================= host orchestration =================
extern "C" void kernel_launch(void* const* d_in, const int* in_sizes, int n_in,
                              void* d_out, int out_size)
{
    const float* node_features = (const float*)d_in[0];
    const int*   edge_index    = (const int*)d_in[1];
    const float* edge_weights  = (const float*)d_in[2];
    const float* time_steps    = (const float*)d_in[3];
    const float* w_enc   = (const float*)d_in[4];
    const float* b_enc   = (const float*)d_in[5];
    const float* g_enc   = (const float*)d_in[6];
    const float* be_enc  = (const float*)d_in[7];
    const float* w_time  = (const float*)d_in[8];
    const float* b_time  = (const float*)d_in[9];
    const float* g_time  = (const float*)d_in[10];
    const float* be_time = (const float*)d_in[11];
    const float* wm  = (const float*)d_in[12];
    const float* bm  = (const float*)d_in[13];
    const float* gm  = (const float*)d_in[14];
    const float* bem = (const float*)d_in[15];
    const float* wu  = (const float*)d_in[16];
    const float* bu  = (const float*)d_in[17];
    const float* gu  = (const float*)d_in[18];
    const float* beu = (const float*)d_in[19];
    const float* wg  = (const float*)d_in[20];
    const float* bg  = (const float*)d_in[21];
    const float* w_out = (const float*)d_in[22];
    const float* b_out = (const float*)d_in[23];
    float* out = (float*)d_out;

    float *p_h, *p_C, *p_tw, *p_b320;
    __nv_bfloat16 *p_ah, *p_al, *p_hh, *p_hl, *p_uh, *p_ul;
    __nv_bfloat16 *p_weh, *p_wel, *p_wmh, *p_wml, *p_wuh, *p_wul, *p_woh, *p_wol;
    cudaGetSymbolAddress((void**)&p_h, g_h);
    cudaGetSymbolAddress((void**)&p_C, g_C320);
    cudaGetSymbolAddress((void**)&p_tw, g_tw);
    cudaGetSymbolAddress((void**)&p_b320, g_bias320);
    cudaGetSymbolAddress((void**)&p_ah, g_ah);
    cudaGetSymbolAddress((void**)&p_al, g_al);
    cudaGetSymbolAddress((void**)&p_hh, g_hh);
    cudaGetSymbolAddress((void**)&p_hl, g_hl);
    cudaGetSymbolAddress((void**)&p_uh, g_uh);
    cudaGetSymbolAddress((void**)&p_ul, g_ul);
    cudaGetSymbolAddress((void**)&p_weh, g_weh);
    cudaGetSymbolAddress((void**)&p_wel, g_wel);
    cudaGetSymbolAddress((void**)&p_wmh, g_wmh);
    cudaGetSymbolAddress((void**)&p_wml, g_wml);
    cudaGetSymbolAddress((void**)&p_wuh, g_wuh);
    cudaGetSymbolAddress((void**)&p_wul, g_wul);
    cudaGetSymbolAddress((void**)&p_woh, g_woh);
    cudaGetSymbolAddress((void**)&p_wol, g_wol);

    const int GBM = (N_NODES + 127) / 128;                   // 782
    const int NODE_WARP_BLOCKS = (N_NODES * 32 + 255) / 256; // 12500
    const int EDGE_WARP_BLOCKS = (N_EDGES * 32 + 255) / 256; // 100000

    const int SM160 = 128 * 160 * 4 + 1024;   // 82944
    const int SM128 = 128 * 128 * 4 + 1024;   // 66560
    cudaFuncSetAttribute(gemm_tc<128, 128, 1>, cudaFuncAttributeMaxDynamicSharedMemorySize, SM128);
    cudaFuncSetAttribute(gemm_tc<160, 192, 0>, cudaFuncAttributeMaxDynamicSharedMemorySize, SM160);
    cudaFuncSetAttribute(gemm_tc<160, 320, 2>, cudaFuncAttributeMaxDynamicSharedMemorySize, SM160);
    cudaFuncSetAttribute(gemm_tc<128, 192, 3>, cudaFuncAttributeMaxDynamicSharedMemorySize, SM128);

    // degrees (constant across layers)
    zero_cnt<<<(N_NODES + 255) / 256, 256>>>();
    degree_kernel<<<(N_EDGES + 255) / 256, 256>>>(edge_index);

    // split inputs/weights for encoder
    split_w<<<(N_NODES * 128 + 255) / 256, 256>>>(node_features, p_ah, p_al, N_NODES, 128, 128);
    split_w<<<(128 * 128 + 255) / 256, 256>>>(w_enc, p_weh, p_wel, 128, 128, 128);
    // encoder GEMM + fused LN/relu + time encoder + h split
    gemm_tc<128, 128, 1><<<dim3(1, GBM), 256, SM128>>>(
        p_ah, p_al, p_weh, p_wel, b_enc, p_h, 160,
        g_enc, be_enc, time_steps, w_time, b_time, g_time, be_time, nullptr);

    for (int l = 0; l < 2; l++) {
        split_msg<<<(320 * 192 + 255) / 256, 256>>>(wm + (size_t)l * 160 * 320, bm + l * 160);
        gemm_tc<160, 192, 0><<<dim3(2, GBM), 256, SM160>>>(
            p_hh, p_hl, p_wmh, p_wml, p_b320, p_C, 320,
            nullptr, nullptr, nullptr, nullptr, nullptr, nullptr, nullptr, nullptr);
        zero_msum<<<4096, 256>>>();
        edge_kernel<<<EDGE_WARP_BLOCKS, 256>>>(edge_index, edge_weights, gm + l * 160, bem + l * 160);
        node1_kernel<<<NODE_WARP_BLOCKS, 256>>>(wg + l * 160, bg + l);
        split_w<<<(160 * 320 + 255) / 256, 256>>>(wu + (size_t)l * 160 * 320, p_wuh, p_wul, 160, 320, 320);
        gemm_tc<160, 320, 2><<<dim3(1, GBM), 256, SM160>>>(
            p_uh, p_ul, p_wuh, p_wul, bu + l * 160, nullptr, 0,
            gu + l * 160, beu + l * 160, p_tw, nullptr, nullptr, nullptr, nullptr, p_h);
    }

    // output projection + fused row-normalize
    split_w<<<(128 * 192 + 255) / 256, 256>>>(w_out, p_woh, p_wol, 128, 160, 192);
    gemm_tc<128, 192, 3><<<dim3(1, GBM), 256, SM128>>>(
        p_hh, p_hl, p_woh, p_wol, b_out, out, 128,
        nullptr, nullptr, nullptr, nullptr, nullptr, nullptr, nullptr, nullptr);
}

// round 8
// speedup vs baseline: 1.8358x; 1.0165x over previous
#include <cuda_runtime.h>
#include <cuda_bf16.h>
#include <cuda_fp16.h>
#include <math.h>
#include <stdint.h>

#define N_NODES 100000
#define NROWS_PAD 100096          // 782 * 128
#define N_EDGES 800000
#define LN_EPS 1e-5f

// ================= scratch (device globals; no allocation allowed) =================
__device__ float g_h[(size_t)N_NODES * 160];      // node state fp32
__device__ __half g_AB[(size_t)NROWS_PAD * 320];  // message A|B fp16 (edge kernel input, L2-resident)
__device__ float g_msum[(size_t)N_NODES * 160];   // scatter-add accumulator
__device__ float g_cnt[N_NODES];                  // in-degree
__device__ float g_tw[N_NODES];                   // gate
__device__ float g_bias320[320];                  // [bm | 0]

// bf16 hi/lo pre-split GEMM A operands
__device__ __align__(16) __nv_bfloat16 g_ah[(size_t)NROWS_PAD * 128], g_al[(size_t)NROWS_PAD * 128];   // node_features
__device__ __align__(16) __nv_bfloat16 g_hh[(size_t)NROWS_PAD * 192], g_hl[(size_t)NROWS_PAD * 192];   // h (K=160 pad 192)
__device__ __align__(16) __nv_bfloat16 g_uh[(size_t)NROWS_PAD * 320], g_ul[(size_t)NROWS_PAD * 320];   // U=[h|msg]

// bf16 hi/lo split weights (zero-padded K)
__device__ __align__(16) __nv_bfloat16 g_weh[128 * 128], g_wel[128 * 128];   // encoder
__device__ __align__(16) __nv_bfloat16 g_wmh[320 * 192], g_wml[320 * 192];   // message
__device__ __align__(16) __nv_bfloat16 g_wuh[160 * 320], g_wul[160 * 320];   // update
__device__ __align__(16) __nv_bfloat16 g_woh[128 * 192], g_wol[128 * 192];   // output

// ================= helpers =================
__device__ __forceinline__ uint32_t smem_u32(const void* p) {
    uint32_t a;
    asm("{ .reg .u64 t; cvta.to.shared.u64 t, %1; cvt.u32.u64 %0, t; }" : "=r"(a) : "l"(p));
    return a;
}
#define SWZ128(o) ((o) ^ (((o) >> 3) & 0x70))

__device__ __forceinline__ void cpa16(uint32_t dst, const void* src) {
    asm volatile("cp.async.cg.shared.global [%0], [%1], 16;" :: "r"(dst), "l"(src));
}
#define CP_COMMIT() asm volatile("cp.async.commit_group;" ::: "memory")
#define CP_WAIT0()  asm volatile("cp.async.wait_group 0;" ::: "memory")

__device__ __forceinline__ void ldsm4(uint32_t* r, uint32_t addr) {
    asm volatile("ldmatrix.sync.aligned.m8n8.x4.shared.b16 {%0,%1,%2,%3}, [%4];"
        : "=r"(r[0]), "=r"(r[1]), "=r"(r[2]), "=r"(r[3]) : "r"(addr));
}
__device__ __forceinline__ void mma16816(float* d, const uint32_t* a, const uint32_t* b) {
    asm volatile("mma.sync.aligned.m16n8k16.row.col.f32.bf16.bf16.f32 "
        "{%0,%1,%2,%3},{%4,%5,%6,%7},{%8,%9},{%0,%1,%2,%3};"
        : "+f"(d[0]), "+f"(d[1]), "+f"(d[2]), "+f"(d[3])
        : "r"(a[0]), "r"(a[1]), "r"(a[2]), "r"(a[3]), "r"(b[0]), "r"(b[1]));
}
__device__ __forceinline__ void split2(float a, float b, uint32_t& hi, uint32_t& lo) {
    __nv_bfloat16 ha = __float2bfloat16(a), hb = __float2bfloat16(b);
    __nv_bfloat16 la = __float2bfloat16(a - __bfloat162float(ha));
    __nv_bfloat16 lb = __float2bfloat16(b - __bfloat162float(hb));
    hi = (uint32_t)__bfloat16_as_ushort(ha) | ((uint32_t)__bfloat16_as_ushort(hb) << 16);
    lo = (uint32_t)__bfloat16_as_ushort(la) | ((uint32_t)__bfloat16_as_ushort(lb) << 16);
}
__device__ __forceinline__ void st_split1(__nv_bfloat16* H, __nv_bfloat16* L, size_t idx, float v) {
    __nv_bfloat16 h = __float2bfloat16(v);
    H[idx] = h;
    L[idx] = __float2bfloat16(v - __bfloat162float(h));
}
__device__ __forceinline__ void st_split4(__nv_bfloat16* H, __nv_bfloat16* L, size_t idx, float4 v) {
    uint2 hp, lp;
    split2(v.x, v.y, hp.x, lp.x);
    split2(v.z, v.w, hp.y, lp.y);
    *(uint2*)(H + idx) = hp;
    *(uint2*)(L + idx) = lp;
}
__device__ __forceinline__ float wsum(float v) {
#pragma unroll
    for (int o = 16; o; o >>= 1) v += __shfl_xor_sync(0xffffffffu, v, o);
    return v;
}
__device__ __forceinline__ void red4(float* p, float4 v) {
    asm volatile("red.global.add.v4.f32 [%0], {%1,%2,%3,%4};"
                 :: "l"(p), "f"(v.x), "f"(v.y), "f"(v.z), "f"(v.w) : "memory");
}

// ================= tensor-core GEMM (mma.sync bf16x3 split), fused epilogues ======
// D[128, NT] tile = X[128, KPAD] @ W[NT, KPAD]^T (pre-split bf16 hi/lo operands).  EPI:
//   0: bias + store fp16 to g_AB (+n0 col offset, stride 320)         (message precompute)
//   1: bias + LN(NT)+relu -> Y cols 0..127 (ldy) + g_hh/g_hl split; time enc col 128+lane
//   2: bias + LN(NT)+relu + gate blend into w0 + g_hh/g_hl split (node update)
//   3: bias + row L2-normalize -> Y (output projection)
template<int NT, int KPAD, int EPI>
__global__ __launch_bounds__(256, 2) void gemm_tc(
    const __nv_bfloat16* __restrict__ Xh, const __nv_bfloat16* __restrict__ Xl,
    const __nv_bfloat16* __restrict__ Wh, const __nv_bfloat16* __restrict__ Wl,
    const float* __restrict__ bias,
    float* __restrict__ Y, int ldy,
    const float* __restrict__ a0, const float* __restrict__ a1,
    const float* __restrict__ a2, const float* __restrict__ a3,
    const float* __restrict__ a4, const float* __restrict__ a5,
    const float* __restrict__ a6,
    float* __restrict__ w0)
{
    extern __shared__ __align__(16) char dsm[];
    char* base = (char*)((((uintptr_t)dsm) + 1023) & ~(uintptr_t)1023);
    const uint32_t sb = smem_u32(base);
    constexpr int A_HI = 0, A_LO = 16384, B_HI = 32768;
    constexpr int B_LO = 32768 + NT * 128;
    constexpr int NW = NT / 2;          // cols per warp (N-dim)
    constexpr int NTILES = NW / 8;      // 8-col tiles per warp (even: 8 or 10)
    const int tid = threadIdx.x, wid = tid >> 5, lane = tid & 31;
    const int wm = wid & 3, wn = wid >> 2;
    const int bm0 = blockIdx.y * 128, n0 = blockIdx.x * NT;

    float acc[2][NTILES][4];
#pragma unroll
    for (int m = 0; m < 2; m++)
#pragma unroll
        for (int t = 0; t < NTILES; t++)
#pragma unroll
            for (int j = 0; j < 4; j++) acc[m][t][j] = 0.f;

    constexpr int NCHUNK = KPAD / 64;
    for (int ch = 0; ch < NCHUNK; ch++) {
        const int c0 = ch * 64;
        // ---- A tile: 128 rows x 64 cols bf16 (hi+lo), cp.async 16B segments ----
#pragma unroll
        for (int s = tid; s < 128 * 8; s += 256) {
            int r = s >> 3, i = s & 7;
            uint32_t off = SWZ128((uint32_t)(r * 128 + i * 16));
            const __nv_bfloat16* srcH = Xh + (size_t)(bm0 + r) * KPAD + c0 + i * 8;
            const __nv_bfloat16* srcL = Xl + (size_t)(bm0 + r) * KPAD + c0 + i * 8;
            cpa16(sb + A_HI + off, srcH);
            cpa16(sb + A_LO + off, srcL);
        }
        // ---- B tile: NT rows x 64 cols (hi+lo) ----
        for (int s = tid; s < NT * 8; s += 256) {
            int r = s >> 3, i = s & 7;
            uint32_t off = SWZ128((uint32_t)(r * 128 + i * 16));
            const __nv_bfloat16* srcH = Wh + (size_t)(n0 + r) * KPAD + c0 + i * 8;
            const __nv_bfloat16* srcL = Wl + (size_t)(n0 + r) * KPAD + c0 + i * 8;
            cpa16(sb + B_HI + off, srcH);
            cpa16(sb + B_LO + off, srcL);
        }
        CP_COMMIT();
        CP_WAIT0();
        __syncthreads();

        // ---- compute: 4 k16 steps over this 64-col chunk ----
#pragma unroll
        for (int ks = 0; ks < 4; ks++) {
            uint32_t ah[2][4], al[2][4];
            const int arow = wm * 32 + (lane & 15);
            const int akb = ks * 32 + ((lane >> 4) << 4);
            {
                uint32_t o0 = SWZ128((uint32_t)(arow * 128 + akb));
                ldsm4(ah[0], sb + A_HI + o0);
                ldsm4(al[0], sb + A_LO + o0);
                uint32_t o1 = SWZ128((uint32_t)((arow + 16) * 128 + akb));
                ldsm4(ah[1], sb + A_HI + o1);
                ldsm4(al[1], sb + A_LO + o1);
            }
            const int q = lane >> 3;
            const int browb = wn * NW + ((q >> 1) << 3) + (lane & 7);
            const int bkb = ks * 32 + (q & 1) * 16;
#pragma unroll
            for (int nt = 0; nt < NTILES; nt += 2) {
                uint32_t bo = SWZ128((uint32_t)((browb + nt * 8) * 128 + bkb));
                uint32_t bh4[4], bl4[4];
                ldsm4(bh4, sb + B_HI + bo);
                ldsm4(bl4, sb + B_LO + bo);
                mma16816(acc[0][nt], ah[0], bh4);
                mma16816(acc[0][nt], ah[0], bl4);
                mma16816(acc[0][nt], al[0], bh4);
                mma16816(acc[1][nt], ah[1], bh4);
                mma16816(acc[1][nt], ah[1], bl4);
                mma16816(acc[1][nt], al[1], bh4);
                mma16816(acc[0][nt + 1], ah[0], bh4 + 2);
                mma16816(acc[0][nt + 1], ah[0], bl4 + 2);
                mma16816(acc[0][nt + 1], al[0], bh4 + 2);
                mma16816(acc[1][nt + 1], ah[1], bh4 + 2);
                mma16816(acc[1][nt + 1], ah[1], bl4 + 2);
                mma16816(acc[1][nt + 1], al[1], bh4 + 2);
            }
        }
        __syncthreads();
    }

    // ---------------- stage D in SMEM (reuse buffers), then row-wise epilogue -----
    float* Dsm = (float*)base;   // [128][NT]
#pragma unroll
    for (int mb = 0; mb < 2; mb++) {
        const int r0 = wm * 32 + mb * 16 + (lane >> 2);
        const int c0 = wn * NW + (lane & 3) * 2;
#pragma unroll
        for (int nt = 0; nt < NTILES; nt++) {
            *(float2*)&Dsm[r0 * NT + c0 + nt * 8] = make_float2(acc[mb][nt][0], acc[mb][nt][1]);
            *(float2*)&Dsm[(r0 + 8) * NT + c0 + nt * 8] = make_float2(acc[mb][nt][2], acc[mb][nt][3]);
        }
    }
    __syncthreads();

    constexpr int NJ = NT / 32;   // elements per lane per row
    for (int rr = 0; rr < 16; rr++) {
        const int r = wid * 16 + rr;
        const int gr = bm0 + r;
        const bool rv = gr < N_NODES;
        float v[NJ];
#pragma unroll
        for (int j = 0; j < NJ; j++) {
            int c = lane + 32 * j;
            v[j] = Dsm[r * NT + c] + bias[(EPI == 0 ? n0 : 0) + c];
        }

        if (EPI == 0) {
            if (rv) {
#pragma unroll
                for (int j = 0; j < NJ; j++)
                    g_AB[(size_t)gr * 320 + n0 + lane + 32 * j] = __float2half(v[j]);
            }
        } else if (EPI == 1 || EPI == 2) {
            float s = 0.f, q = 0.f;
#pragma unroll
            for (int j = 0; j < NJ; j++) { s += v[j]; q += v[j] * v[j]; }
            float mean = wsum(s) * (1.f / NT);
            float var = wsum(q) * (1.f / NT) - mean * mean;
            float rstd = rsqrtf(var + LN_EPS);
            if (rv) {
                if (EPI == 1) {
#pragma unroll
                    for (int j = 0; j < NJ; j++) {
                        int c = lane + 32 * j;
                        float hv = fmaxf(0.f, (v[j] - mean) * rstd * a0[c] + a1[c]);
                        Y[(size_t)gr * ldy + c] = hv;
                        st_split1(g_hh, g_hl, (size_t)gr * 192 + c, hv);
                    }
                    // time encoder (32 dims, one per lane)
                    float t0 = a2[gr];
                    float tv = t0 * a3[lane] + a4[lane];
                    float tm = wsum(tv) * (1.f / 32.f);
                    float td = tv - tm;
                    float tvar = wsum(td * td) * (1.f / 32.f);
                    float tr = rsqrtf(tvar + LN_EPS);
                    float to = fmaxf(0.f, td * tr * a5[lane] + a6[lane]);
                    Y[(size_t)gr * ldy + 128 + lane] = to;
                    st_split1(g_hh, g_hl, (size_t)gr * 192 + 128 + lane, to);
                    g_hh[(size_t)gr * 192 + 160 + lane] = __float2bfloat16(0.f);
                    g_hl[(size_t)gr * 192 + 160 + lane] = __float2bfloat16(0.f);
                } else {
                    float tw = a2[gr];
#pragma unroll
                    for (int j = 0; j < NJ; j++) {
                        int c = lane + 32 * j;
                        float hn = fmaxf(0.f, (v[j] - mean) * rstd * a0[c] + a1[c]);
                        float ho = w0[(size_t)gr * 160 + c];
                        float hv = tw * hn + (1.f - tw) * ho;
                        w0[(size_t)gr * 160 + c] = hv;
                        st_split1(g_hh, g_hl, (size_t)gr * 192 + c, hv);
                    }
                    g_hh[(size_t)gr * 192 + 160 + lane] = __float2bfloat16(0.f);
                    g_hl[(size_t)gr * 192 + 160 + lane] = __float2bfloat16(0.f);
                }
            }
        } else {  // EPI == 3
            float q = 0.f;
#pragma unroll
            for (int j = 0; j < NJ; j++) q += v[j] * v[j];
            float sc = 1.f / fmaxf(sqrtf(wsum(q)), 1e-12f);
            if (rv) {
#pragma unroll
                for (int j = 0; j < NJ; j++)
                    Y[(size_t)gr * ldy + lane + 32 * j] = v[j] * sc;
            }
        }
    }
}

// ================= weight / input split kernels =================
__global__ void split_w(const float* __restrict__ W, __nv_bfloat16* __restrict__ H,
                        __nv_bfloat16* __restrict__ L, int NR, int K, int KPAD) {
    int t = blockIdx.x * blockDim.x + threadIdx.x;
    if (t >= NR * KPAD) return;
    int r = t / KPAD, c = t - r * KPAD;
    float v = (c < K) ? W[r * K + c] : 0.f;
    __nv_bfloat16 h = __float2bfloat16(v);
    H[t] = h;
    L[t] = __float2bfloat16(v - __bfloat162float(h));
}
__global__ void split_msg(const float* __restrict__ wm, const float* __restrict__ bm) {
    int t = blockIdx.x * blockDim.x + threadIdx.x;
    if (t < 320 * 192) {
        int r = t / 192, c = t - r * 192;
        float v = 0.f;
        if (c < 160) v = (r < 160) ? wm[r * 320 + c] : wm[(r - 160) * 320 + 160 + c];
        __nv_bfloat16 h = __float2bfloat16(v);
        g_wmh[t] = h;
        g_wml[t] = __float2bfloat16(v - __bfloat162float(h));
    }
    if (t < 320) g_bias320[t] = (t < 160) ? bm[t] : 0.f;
}

// ================= zero / degree =================
__global__ void zero_cnt() {
    int i = blockIdx.x * blockDim.x + threadIdx.x;
    if (i < N_NODES) g_cnt[i] = 0.f;
}
__global__ void zero_msum() {
    int i = blockIdx.x * blockDim.x + threadIdx.x;
    int st = gridDim.x * blockDim.x;
    float4* p = (float4*)g_msum;
    const int n4 = N_NODES * 40;
    for (int k = i; k < n4; k += st) p[k] = make_float4(0.f, 0.f, 0.f, 0.f);
}
__global__ void degree_kernel(const int* __restrict__ ei) {
    int e = blockIdx.x * blockDim.x + threadIdx.x;
    if (e < N_EDGES) atomicAdd(&g_cnt[ei[N_EDGES + e]], 1.0f);
}

// ================= edge pass (fp16 gather, fp32 atomic scatter) =================
// one warp per edge; lanes 0..19 each own 8 contiguous channels (16B fp16)
__global__ void edge_kernel(const int* __restrict__ ei, const float* __restrict__ ew,
                            const float* __restrict__ gmv, const float* __restrict__ bemv)
{
    int w = (blockIdx.x * blockDim.x + threadIdx.x) >> 5;
    int lane = threadIdx.x & 31;
    if (w >= N_EDGES) return;
    int src = ei[w];
    int dst = ei[N_EDGES + w];
    float ewt = ew[w];
    const bool act = lane < 20;

    float v[8];
#pragma unroll
    for (int k = 0; k < 8; k++) v[k] = 0.f;
    if (act) {
        const __half* S = g_AB + (size_t)src * 320 + lane * 8;
        const __half* D = g_AB + (size_t)dst * 320 + 160 + lane * 8;
        uint4 sv = *(const uint4*)S;
        uint4 dv = *(const uint4*)D;
        const __half2* sh = (const __half2*)&sv;
        const __half2* dh = (const __half2*)&dv;
#pragma unroll
        for (int k = 0; k < 4; k++) {
            float2 a = __half22float2(sh[k]);
            float2 b = __half22float2(dh[k]);
            v[2 * k + 0] = a.x + b.x;
            v[2 * k + 1] = a.y + b.y;
        }
    }

    float s = 0.f;
#pragma unroll
    for (int k = 0; k < 8; k++) s += v[k];
    float mean = wsum(s) * (1.0f / 160.0f);

    float q = 0.f;
    if (act) {
#pragma unroll
        for (int k = 0; k < 8; k++) q += (v[k] - mean) * (v[k] - mean);
    }
    float var = wsum(q) * (1.0f / 160.0f);
    float rstd = rsqrtf(var + LN_EPS);

    if (act) {
        const int c0 = lane * 8;
        float4 g0 = ((const float4*)gmv)[2 * lane];
        float4 g1 = ((const float4*)gmv)[2 * lane + 1];
        float4 b0 = ((const float4*)bemv)[2 * lane];
        float4 b1 = ((const float4*)bemv)[2 * lane + 1];
        float* basep = g_msum + (size_t)dst * 160 + c0;
        float4 o0, o1;
        o0.x = fmaxf(0.f, (v[0] - mean) * rstd * g0.x + b0.x) * ewt;
        o0.y = fmaxf(0.f, (v[1] - mean) * rstd * g0.y + b0.y) * ewt;
        o0.z = fmaxf(0.f, (v[2] - mean) * rstd * g0.z + b0.z) * ewt;
        o0.w = fmaxf(0.f, (v[3] - mean) * rstd * g0.w + b0.w) * ewt;
        o1.x = fmaxf(0.f, (v[4] - mean) * rstd * g1.x + b1.x) * ewt;
        o1.y = fmaxf(0.f, (v[5] - mean) * rstd * g1.y + b1.y) * ewt;
        o1.z = fmaxf(0.f, (v[6] - mean) * rstd * g1.z + b1.z) * ewt;
        o1.w = fmaxf(0.f, (v[7] - mean) * rstd * g1.w + b1.w) * ewt;
        red4(basep, o0);
        red4(basep + 4, o1);
    }
}

// ================= node pass 1: U=[h|messages] split to bf16, gate tw =============
__global__ void node1_kernel(const float* __restrict__ wgv, const float* __restrict__ bgv) {
    int n = (blockIdx.x * blockDim.x + threadIdx.x) >> 5;
    int lane = threadIdx.x & 31;
    if (n >= N_NODES) return;

    float c = g_cnt[n];
    float inv = (c > 0.f) ? 1.f / (c + 1e-8f) : 0.f;

    const float4* H = (const float4*)(g_h + (size_t)n * 160);
    const float4* Ms = (const float4*)(g_msum + (size_t)n * 160);
    const bool two = lane < 8;
    const size_t ub = (size_t)n * 320;

    float dotp = 0.f;
    {
        float4 h = H[lane];
        st_split4(g_uh, g_ul, ub + 4 * lane, h);
        float4 m = Ms[lane];
        float4 mm = make_float4(m.x * inv, m.y * inv, m.z * inv, m.w * inv);
        st_split4(g_uh, g_ul, ub + 160 + 4 * lane, mm);
        float4 wg = ((const float4*)wgv)[lane];
        dotp = h.x * wg.x + h.y * wg.y + h.z * wg.z + h.w * wg.w;
    }
    if (two) {
        float4 h = H[lane + 32];
        st_split4(g_uh, g_ul, ub + 128 + 4 * lane, h);
        float4 m = Ms[lane + 32];
        float4 mm = make_float4(m.x * inv, m.y * inv, m.z * inv, m.w * inv);
        st_split4(g_uh, g_ul, ub + 160 + 128 + 4 * lane, mm);
        float4 wg = ((const float4*)wgv)[lane + 32];
        dotp += h.x * wg.x + h.y * wg.y + h.z * wg.z + h.w * wg.w;
    }
    float tot = wsum(dotp);
    if (lane == 0) g_tw[n] = 1.f / (1.f + expf(-(tot + bgv[0])));
}

// ================= host orchestration =================
extern "C" void kernel_launch(void* const* d_in, const int* in_sizes, int n_in,
                              void* d_out, int out_size)
{
    const float* node_features = (const float*)d_in[0];
    const int*   edge_index    = (const int*)d_in[1];
    const float* edge_weights  = (const float*)d_in[2];
    const float* time_steps    = (const float*)d_in[3];
    const float* w_enc   = (const float*)d_in[4];
    const float* b_enc   = (const float*)d_in[5];
    const float* g_enc   = (const float*)d_in[6];
    const float* be_enc  = (const float*)d_in[7];
    const float* w_time  = (const float*)d_in[8];
    const float* b_time  = (const float*)d_in[9];
    const float* g_time  = (const float*)d_in[10];
    const float* be_time = (const float*)d_in[11];
    const float* wm  = (const float*)d_in[12];
    const float* bm  = (const float*)d_in[13];
    const float* gm  = (const float*)d_in[14];
    const float* bem = (const float*)d_in[15];
    const float* wu  = (const float*)d_in[16];
    const float* bu  = (const float*)d_in[17];
    const float* gu  = (const float*)d_in[18];
    const float* beu = (const float*)d_in[19];
    const float* wg  = (const float*)d_in[20];
    const float* bg  = (const float*)d_in[21];
    const float* w_out = (const float*)d_in[22];
    const float* b_out = (const float*)d_in[23];
    float* out = (float*)d_out;

    float *p_h, *p_tw, *p_b320;
    __nv_bfloat16 *p_ah, *p_al, *p_hh, *p_hl, *p_uh, *p_ul;
    __nv_bfloat16 *p_weh, *p_wel, *p_wmh, *p_wml, *p_wuh, *p_wul, *p_woh, *p_wol;
    cudaGetSymbolAddress((void**)&p_h, g_h);
    cudaGetSymbolAddress((void**)&p_tw, g_tw);
    cudaGetSymbolAddress((void**)&p_b320, g_bias320);
    cudaGetSymbolAddress((void**)&p_ah, g_ah);
    cudaGetSymbolAddress((void**)&p_al, g_al);
    cudaGetSymbolAddress((void**)&p_hh, g_hh);
    cudaGetSymbolAddress((void**)&p_hl, g_hl);
    cudaGetSymbolAddress((void**)&p_uh, g_uh);
    cudaGetSymbolAddress((void**)&p_ul, g_ul);
    cudaGetSymbolAddress((void**)&p_weh, g_weh);
    cudaGetSymbolAddress((void**)&p_wel, g_wel);
    cudaGetSymbolAddress((void**)&p_wmh, g_wmh);
    cudaGetSymbolAddress((void**)&p_wml, g_wml);
    cudaGetSymbolAddress((void**)&p_wuh, g_wuh);
    cudaGetSymbolAddress((void**)&p_wul, g_wul);
    cudaGetSymbolAddress((void**)&p_woh, g_woh);
    cudaGetSymbolAddress((void**)&p_wol, g_wol);

    const int GBM = (N_NODES + 127) / 128;                   // 782
    const int NODE_WARP_BLOCKS = (N_NODES * 32 + 255) / 256; // 12500
    const int EDGE_WARP_BLOCKS = (N_EDGES * 32 + 255) / 256; // 100000

    const int SM160 = 128 * 160 * 4 + 1024;   // 82944
    const int SM128 = 128 * 128 * 4 + 1024;   // 66560
    cudaFuncSetAttribute(gemm_tc<128, 128, 1>, cudaFuncAttributeMaxDynamicSharedMemorySize, SM128);
    cudaFuncSetAttribute(gemm_tc<160, 192, 0>, cudaFuncAttributeMaxDynamicSharedMemorySize, SM160);
    cudaFuncSetAttribute(gemm_tc<160, 320, 2>, cudaFuncAttributeMaxDynamicSharedMemorySize, SM160);
    cudaFuncSetAttribute(gemm_tc<128, 192, 3>, cudaFuncAttributeMaxDynamicSharedMemorySize, SM128);

    // degrees (constant across layers)
    zero_cnt<<<(N_NODES + 255) / 256, 256>>>();
    degree_kernel<<<(N_EDGES + 255) / 256, 256>>>(edge_index);

    // split inputs/weights for encoder
    split_w<<<(N_NODES * 128 + 255) / 256, 256>>>(node_features, p_ah, p_al, N_NODES, 128, 128);
    split_w<<<(128 * 128 + 255) / 256, 256>>>(w_enc, p_weh, p_wel, 128, 128, 128);
    // encoder GEMM + fused LN/relu + time encoder + h split
    gemm_tc<128, 128, 1><<<dim3(1, GBM), 256, SM128>>>(
        p_ah, p_al, p_weh, p_wel, b_enc, p_h, 160,
        g_enc, be_enc, time_steps, w_time, b_time, g_time, be_time, nullptr);

    for (int l = 0; l < 2; l++) {
        split_msg<<<(320 * 192 + 255) / 256, 256>>>(wm + (size_t)l * 160 * 320, bm + l * 160);
        gemm_tc<160, 192, 0><<<dim3(2, GBM), 256, SM160>>>(
            p_hh, p_hl, p_wmh, p_wml, p_b320, nullptr, 0,
            nullptr, nullptr, nullptr, nullptr, nullptr, nullptr, nullptr, nullptr);
        zero_msum<<<4096, 256>>>();
        edge_kernel<<<EDGE_WARP_BLOCKS, 256>>>(edge_index, edge_weights, gm + l * 160, bem + l * 160);
        node1_kernel<<<NODE_WARP_BLOCKS, 256>>>(wg + l * 160, bg + l);
        split_w<<<(160 * 320 + 255) / 256, 256>>>(wu + (size_t)l * 160 * 320, p_wuh, p_wul, 160, 320, 320);
        gemm_tc<160, 320, 2><<<dim3(1, GBM), 256, SM160>>>(
            p_uh, p_ul, p_wuh, p_wul, bu + l * 160, nullptr, 0,
            gu + l * 160, beu + l * 160, p_tw, nullptr, nullptr, nullptr, nullptr, p_h);
    }

    // output projection + fused row-normalize
    split_w<<<(128 * 192 + 255) / 256, 256>>>(w_out, p_woh, p_wol, 128, 160, 192);
    gemm_tc<128, 192, 3><<<dim3(1, GBM), 256, SM128>>>(
        p_hh, p_hl, p_woh, p_wol, b_out, out, 128,
        nullptr, nullptr, nullptr, nullptr, nullptr, nullptr, nullptr, nullptr);
}